// round 13
// baseline (speedup 1.0000x reference)
#include <cuda_runtime.h>
#include <cuda_bf16.h>
#include <cstdint>
#include <cstddef>

#define BB 16
#define NN 8192
#define SS 1024
#define KK 32
#define R2C 0.04f          /* float(0.2**2) */
#define EPSC 1e-5f
#define MTOT (BB*SS*KK)    /* 524288 positions */
#define QTOT (BB*SS)       /* 16384 queries */
#define OUT_OFF (BB*SS*3)

typedef unsigned long long ull;

// ---------------- packed f32x2 helpers ----------------------------------------
__device__ __forceinline__ ull fma2(ull a, ull b, ull c) {
    ull d; asm("fma.rn.f32x2 %0,%1,%2,%3;" : "=l"(d) : "l"(a), "l"(b), "l"(c)); return d;
}
__device__ __forceinline__ ull mul2(ull a, ull b) {
    ull d; asm("mul.rn.f32x2 %0,%1,%2;" : "=l"(d) : "l"(a), "l"(b)); return d;
}
__device__ __forceinline__ ull add2(ull a, ull b) {
    ull d; asm("add.rn.f32x2 %0,%1,%2;" : "=l"(d) : "l"(a), "l"(b)); return d;
}
__device__ __forceinline__ ull dup2(float x) {
    ull d; asm("mov.b64 %0,{%1,%1};" : "=l"(d) : "f"(x)); return d;
}
__device__ __forceinline__ ull pk2(float lo, float hi) {
    ull d; asm("mov.b64 %0,{%1,%2};" : "=l"(d) : "f"(lo), "f"(hi)); return d;
}
__device__ __forceinline__ float2 up2(ull v) {
    float2 r; asm("mov.b64 {%0,%1},%2;" : "=f"(r.x), "=f"(r.y) : "l"(v)); return r;
}

// ---------------- HMMA / ldmatrix helpers (baseline PTX, sm_103-safe) ---------
__device__ __forceinline__ uint32_t smem_u32(const void* p) {
    uint32_t a;
    asm("{ .reg .u64 t; cvta.to.shared.u64 t, %1; cvt.u32.u64 %0, t; }" : "=r"(a) : "l"(p));
    return a;
}
__device__ __forceinline__ void ldm4(uint32_t addr, uint32_t* r) {
    asm volatile("ldmatrix.sync.aligned.m8n8.x4.shared.b16 {%0,%1,%2,%3}, [%4];"
                 : "=r"(r[0]), "=r"(r[1]), "=r"(r[2]), "=r"(r[3]) : "r"(addr));
}
__device__ __forceinline__ void mma_f16(float* c, const uint32_t* a, const uint32_t* b) {
    asm volatile(
        "mma.sync.aligned.m16n8k16.row.col.f32.f16.f16.f32 "
        "{%0,%1,%2,%3}, {%4,%5,%6,%7}, {%8,%9}, {%0,%1,%2,%3};"
        : "+f"(c[0]), "+f"(c[1]), "+f"(c[2]), "+f"(c[3])
        : "r"(a[0]), "r"(a[1]), "r"(a[2]), "r"(a[3]), "r"(b[0]), "r"(b[1]));
}

// split fp32 pair -> packed fp16 highs + packed fp16 residuals (a ~= ah + al)
__device__ __forceinline__ void split_f16(float a, float b, uint32_t& hi, uint32_t& lo) {
    asm("{.reg .b16 ha,hb,la,lb;\n"
        " .reg .f32 fa,fb;\n"
        " cvt.rn.f16.f32 ha, %2;\n"
        " cvt.rn.f16.f32 hb, %3;\n"
        " cvt.f32.f16 fa, ha;\n"
        " cvt.f32.f16 fb, hb;\n"
        " sub.f32 fa, %2, fa;\n"
        " sub.f32 fb, %3, fb;\n"
        " cvt.rn.f16.f32 la, fa;\n"
        " cvt.rn.f16.f32 lb, fb;\n"
        " mov.b32 %0, {ha,hb};\n"
        " mov.b32 %1, {la,lb};}"
        : "=r"(hi), "=r"(lo) : "f"(a), "f"(b));
}
__device__ __forceinline__ uint32_t pack_f16(float a, float b) {
    uint32_t r;
    asm("{.reg .b16 x,y; cvt.rn.f16.f32 x,%1; cvt.rn.f16.f32 y,%2; mov.b32 %0,{x,y};}"
        : "=r"(r) : "f"(a), "f"(b));
    return r;
}

// ---------------- device scratch ----------------------------------------------
__device__ int    g_fps[QTOT];
__device__ int    g_idx[(size_t)QTOT*KK];
__device__ float  g_y1[(size_t)MTOT*64];
__device__ float  g_y2[(size_t)MTOT*64];
__device__ float  g_mx[(size_t)128*QTOT];   // [ch][q]
__device__ float  g_mn[(size_t)128*QTOT];
__device__ double g_sum[3][128];
__device__ double g_sq[3][128];
__device__ float  g_scale[3][128];
__device__ float  g_shift[3][128];

// ---------------- init --------------------------------------------------------
__global__ void init_kernel() {
    int t = blockIdx.x * blockDim.x + threadIdx.x;
    if (t < 3 * 128) {
        ((double*)g_sum)[t] = 0.0;
        ((double*)g_sq)[t]  = 0.0;
    }
}

// ---------------- farthest point sampling: 1 barrier/iter --------------------
__global__ __launch_bounds__(1024) void fps_kernel(const float* __restrict__ xyz) {
    int b = blockIdx.x;
    int t = threadIdx.x;
    int lane = t & 31, w = t >> 5;
    const float* xb = xyz + (size_t)b * NN * 3;

    ull px2[4], py2[4], pz2[4];
    float dist[8];
#pragma unroll
    for (int j = 0; j < 4; j++) {
        int p0 = t + (2*j)   * 1024;
        int p1 = t + (2*j+1) * 1024;
        px2[j] = pk2(xb[p0*3+0], xb[p1*3+0]);
        py2[j] = pk2(xb[p0*3+1], xb[p1*3+1]);
        pz2[j] = pk2(xb[p0*3+2], xb[p1*3+2]);
    }
#pragma unroll
    for (int i = 0; i < 8; i++) dist[i] = 1e10f;

    __shared__ ull s_key[2][32];
    int far = 0;
    int buf = 0;

    for (int it = 0; it < SS; it++) {
        if (t == 0) g_fps[b * SS + it] = far;
        float cx = xb[far*3+0], cy = xb[far*3+1], cz = xb[far*3+2];
        ull ncx = dup2(-cx), ncy = dup2(-cy), ncz = dup2(-cz);

        float bestv = -1.0f; int besti = 0;
#pragma unroll
        for (int j = 0; j < 4; j++) {
            ull dx = add2(px2[j], ncx);
            ull dy = add2(py2[j], ncy);
            ull dz = add2(pz2[j], ncz);
            ull d2 = mul2(dx, dx);
            d2 = fma2(dy, dy, d2);
            d2 = fma2(dz, dz, d2);
            float2 dd = up2(d2);
            float n0 = fminf(dist[2*j],   dd.x);
            float n1 = fminf(dist[2*j+1], dd.y);
            dist[2*j] = n0; dist[2*j+1] = n1;
            if (n0 > bestv) { bestv = n0; besti = t + (2*j)   * 1024; }
            if (n1 > bestv) { bestv = n1; besti = t + (2*j+1) * 1024; }
        }

        unsigned bits = __float_as_uint(bestv);
        unsigned mh = __reduce_max_sync(0xffffffffu, bits);
        unsigned ml = __reduce_max_sync(0xffffffffu, (bits == mh) ? ~(unsigned)besti : 0u);
        if (lane == 0) s_key[buf][w] = ((ull)mh << 32) | ml;
        __syncthreads();
        ull k = s_key[buf][lane];
        unsigned h2 = (unsigned)(k >> 32);
        unsigned m2 = __reduce_max_sync(0xffffffffu, h2);
        unsigned l2 = __reduce_max_sync(0xffffffffu, (h2 == m2) ? (unsigned)k : 0u);
        far = (int)(~l2);
        buf ^= 1;
    }
}

// ---------------- gather new_xyz into output ---------------------------------
__global__ void gather_newxyz_kernel(const float* __restrict__ xyz,
                                     float* __restrict__ out) {
    int i = blockIdx.x * blockDim.x + threadIdx.x;
    if (i < QTOT) {
        int b = i >> 10;
        int j = g_fps[i];
        const float* p = xyz + ((size_t)b * NN + j) * 3;
        out[i*3+0] = p[0];
        out[i*3+1] = p[1];
        out[i*3+2] = p[2];
    }
}

// ---------------- ball query: one warp per query, 1-deep prefetch ------------
__global__ void qb_kernel(const float* __restrict__ xyz) {
    int q = (blockIdx.x * blockDim.x + threadIdx.x) >> 5;
    int lane = threadIdx.x & 31;
    int b = q >> 10;
    const float* xb = xyz + (size_t)b * NN * 3;
    int c = g_fps[q];
    float cx = xb[c*3+0], cy = xb[c*3+1], cz = xb[c*3+2];

    int cnt = 0;
    int first = 0;
    bool have_first = false;
    int* out = g_idx + (size_t)q * KK;

    int p = lane;
    float x = xb[p*3+0], y = xb[p*3+1], z = xb[p*3+2];

    for (int base = 0; base < NN; base += 32) {
        float nx = 0.f, ny = 0.f, nz = 0.f;
        if (base + 32 < NN) {
            int pn = base + 32 + lane;
            nx = xb[pn*3+0]; ny = xb[pn*3+1]; nz = xb[pn*3+2];
        }
        float dx = x - cx, dy = y - cy, dz = z - cz;
        float d = dx*dx + dy*dy + dz*dz;
        bool in = (d <= R2C);
        unsigned m = __ballot_sync(0xffffffffu, in);
        if (m) {
            int pos = cnt + __popc(m & ((1u << lane) - 1u));
            if (in && pos < KK) out[pos] = p;
            if (!have_first) { first = base + __ffs(m) - 1; have_first = true; }
            cnt += __popc(m);
            if (cnt >= KK) break;
        }
        p = base + 32 + lane; x = nx; y = ny; z = nz;
    }
    for (int pos = cnt + lane; pos < KK; pos += 32) out[pos] = first;
}

// ---------------- per-channel BN fold ----------------------------------------
__global__ void stats_kernel(int L, const float* __restrict__ gam,
                             const float* __restrict__ bet, int C) {
    int t = threadIdx.x;
    if (t < C) {
        double mean = g_sum[L][t] * (1.0 / (double)MTOT);
        double var  = g_sq[L][t]  * (1.0 / (double)MTOT) - mean * mean;
        float sc = gam[t] * rsqrtf((float)var + EPSC);
        g_scale[L][t] = sc;
        g_shift[L][t] = fmaf(-(float)mean, sc, bet[t]);
    }
}

// shfl butterfly over the 8 rq-lanes (xor 4, 8, 16)
#define RQ_REDUCE(arr, cnt)                                             \
    _Pragma("unroll")                                                   \
    for (int _mask = 4; _mask <= 16; _mask <<= 1)                       \
        _Pragma("unroll")                                               \
        for (int _i = 0; _i < (cnt); _i++)                              \
            (arr)[_i] += __shfl_xor_sync(0xffffffffu, (arr)[_i], _mask);

// bank-conflict swizzle: flip the 16B half with row bit 2
#define SWZ(r) ((((uint32_t)(r) >> 2) & 1u) << 4)

// ---------------- layer 1: HMMA gather-GEMM (K=67 pad 80 -> 64) + stats ------
// fp16 2-term split: A' = [ah(80) | al(80)], B' = [bh(80) ; bh(80)]; 10 chunks.
// k-channel order: 0..63 = points, 64..66 = xyz-norm, 67..79 = zero pad.
__global__ __launch_bounds__(256) void mm1_kernel(
    const float* __restrict__ xyz, const float* __restrict__ points,
    const float* __restrict__ newxyz,
    const float* __restrict__ w, const float* __restrict__ bias)
{
    constexpr int NCH = 64;
    constexpr int ACH = 128 * 32;           // 4096 B per A k-chunk
    constexpr int NKC = 10;
    constexpr int ABYTES = NKC * ACH;       // 40960
    constexpr int BCH = NCH * 32;           // 2048
    constexpr int BBYTES = NKC * BCH;       // 20480
    constexpr int NT8 = 4, NB4 = 2;

    extern __shared__ char dsm[];
    uint32_t raw = smem_u32(dsm);
    uint32_t abase = (raw + 1023) & ~1023u;
    char* sm  = dsm + (abase - raw);
    char* Bsm = sm + ABYTES;
    uint32_t bbase = abase + ABYTES;
    float* sh_bias = (float*)(Bsm + BBYTES);

    int t = threadIdx.x;
    int wid = t >> 5, lane = t & 31;
    size_t pos0 = (size_t)blockIdx.x * 128;

    if (t < NCH) sh_bias[t] = bias[t];

    // ---- stage A: 2 threads per row ----
    {
        int r = t >> 1, h = t & 1;
        size_t pos = pos0 + r;
        int j = g_idx[pos];
        int b = (int)(pos >> 15);
        int s = (int)((pos >> 5) & 1023);
        uint32_t sw = SWZ(r);
        const float4* prow = (const float4*)(points + ((size_t)b * NN + j) * 64) + h * 8;
#pragma unroll
        for (int g = 0; g < 8; g++) {
            float4 v = prow[g];
            int c = h * 32 + g * 4;
            uint32_t h01, l01, h23, l23;
            split_f16(v.x, v.y, h01, l01);
            split_f16(v.z, v.w, h23, l23);
            uint32_t off = (uint32_t)(c >> 4) * ACH + (uint32_t)r * 32
                         + ((uint32_t)((c & 15) * 2) ^ sw);
            *(uint2*)(sm + off)           = make_uint2(h01, h23);   // ah
            *(uint2*)(sm + off + 5 * ACH) = make_uint2(l01, l23);   // al
        }
        if (!h) {
            const float* xr = xyz + ((size_t)b * NN + j) * 3;
            const float* nr = newxyz + ((size_t)b * SS + s) * 3;
            float x0 = xr[0] - nr[0], x1 = xr[1] - nr[1], x2 = xr[2] - nr[2];
            uint32_t h01, l01, h23, l23;
            split_f16(x0, x1, h01, l01);
            split_f16(x2, 0.f, h23, l23);
            uint32_t base = 4 * ACH + (uint32_t)r * 32;
            uint2 z = make_uint2(0u, 0u);
            *(uint2*)(sm + base + (0u ^ sw))            = make_uint2(h01, h23);
            *(uint2*)(sm + base + (8u ^ sw))            = z;
            *(uint2*)(sm + base + (16u ^ sw))           = z;
            *(uint2*)(sm + base + (24u ^ sw))           = z;
            *(uint2*)(sm + base + 5*ACH + (0u ^ sw))    = make_uint2(l01, l23);
            *(uint2*)(sm + base + 5*ACH + (8u ^ sw))    = z;
            *(uint2*)(sm + base + 5*ACH + (16u ^ sw))   = z;
            *(uint2*)(sm + base + 5*ACH + (24u ^ sw))   = z;
        }
    }
    // ---- stage B: w1 rows, permuted channels, single fp16 (replicated) ----
    {
        int r = t >> 2, sub = t & 3;
        uint32_t sw = SWZ(r);
        const float* wr = w + r * 67;
#pragma unroll
        for (int g = 0; g < 5; g++) {
            int kq = sub * 20 + g * 4;
            float v[4];
#pragma unroll
            for (int i = 0; i < 4; i++) {
                int kc = kq + i;
                v[i] = (kc < 64) ? wr[3 + kc] : ((kc < 67) ? wr[kc - 64] : 0.f);
            }
            uint32_t h01 = pack_f16(v[0], v[1]);
            uint32_t h23 = pack_f16(v[2], v[3]);
            uint32_t off = (uint32_t)(kq >> 4) * BCH + (uint32_t)r * 32
                         + ((uint32_t)((kq & 15) * 2) ^ sw);
            *(uint2*)(Bsm + off)           = make_uint2(h01, h23);
            *(uint2*)(Bsm + off + 5 * BCH) = make_uint2(h01, h23);
        }
    }
    __syncthreads();

    int m0 = (wid & 3) * 32;
    int n0 = (wid >> 2) * 32;

    float acc[2][NT8][4];
#pragma unroll
    for (int mi = 0; mi < 2; mi++)
#pragma unroll
        for (int nj = 0; nj < NT8; nj++)
#pragma unroll
            for (int e = 0; e < 4; e++) acc[mi][nj][e] = 0.f;

    uint32_t a_addr[2], b_addr[NB4];
#pragma unroll
    for (int mi = 0; mi < 2; mi++) {
        uint32_t row = (uint32_t)(m0 + mi*16 + (lane & 15));
        a_addr[mi] = abase + row * 32 + (((uint32_t)(lane >> 4) << 4) ^ SWZ(row));
    }
#pragma unroll
    for (int nj = 0; nj < NB4; nj++) {
        uint32_t row = (uint32_t)(n0 + nj*16 + (lane & 7) + ((lane >> 4) << 3));
        b_addr[nj] = bbase + row * 32 + ((((uint32_t)(lane >> 3) & 1u) << 4) ^ SWZ(row));
    }

#pragma unroll
    for (int kc = 0; kc < NKC; kc++) {
        uint32_t af[2][4];
        ldm4(a_addr[0] + kc * ACH, af[0]);
        ldm4(a_addr[1] + kc * ACH, af[1]);
        uint32_t bf[NT8][2];
#pragma unroll
        for (int nj = 0; nj < NB4; nj++) {
            uint32_t tmp[4];
            ldm4(b_addr[nj] + kc * BCH, tmp);
            bf[2*nj][0] = tmp[0]; bf[2*nj][1] = tmp[1];
            bf[2*nj+1][0] = tmp[2]; bf[2*nj+1][1] = tmp[3];
        }
#pragma unroll
        for (int mi = 0; mi < 2; mi++)
#pragma unroll
            for (int nj = 0; nj < NT8; nj++)
                mma_f16(acc[mi][nj], af[mi], bf[nj]);
    }

    // ---- epilogue: bias + store + shfl-reduced stats ----
    int rq = lane >> 2, cq = (lane & 3) * 2;
    float ps[2*NT8], pq[2*NT8];
#pragma unroll
    for (int nj = 0; nj < NT8; nj++) {
        int col = n0 + nj*8 + cq;
        float b0 = sh_bias[col], b1 = sh_bias[col+1];
        float y00 = acc[0][nj][0] + b0, y01 = acc[0][nj][1] + b1;
        float y10 = acc[0][nj][2] + b0, y11 = acc[0][nj][3] + b1;
        float y20 = acc[1][nj][0] + b0, y21 = acc[1][nj][1] + b1;
        float y30 = acc[1][nj][2] + b0, y31 = acc[1][nj][3] + b1;
        size_t r0 = pos0 + m0 + rq;
        *(float2*)(g_y1 + r0 * 64 + col)        = make_float2(y00, y01);
        *(float2*)(g_y1 + (r0 + 8) * 64 + col)  = make_float2(y10, y11);
        *(float2*)(g_y1 + (r0 + 16) * 64 + col) = make_float2(y20, y21);
        *(float2*)(g_y1 + (r0 + 24) * 64 + col) = make_float2(y30, y31);
        ps[2*nj]   = y00 + y10 + y20 + y30;
        ps[2*nj+1] = y01 + y11 + y21 + y31;
        pq[2*nj]   = y00*y00 + y10*y10 + y20*y20 + y30*y30;
        pq[2*nj+1] = y01*y01 + y11*y11 + y21*y21 + y31*y31;
    }
    RQ_REDUCE(ps, 2*NT8);
    RQ_REDUCE(pq, 2*NT8);
    __syncthreads();
    float* wsum = (float*)sm;              // [8][NCH]
    float* wsq  = wsum + 8 * NCH;
    if (lane < 4) {
#pragma unroll
        for (int nj = 0; nj < NT8; nj++) {
            int col = n0 + nj*8 + cq;
            wsum[wid*NCH + col]   = ps[2*nj];
            wsum[wid*NCH + col+1] = ps[2*nj+1];
            wsq[wid*NCH + col]    = pq[2*nj];
            wsq[wid*NCH + col+1]  = pq[2*nj+1];
        }
    }
    __syncthreads();
    if (t < NCH) {
        int wb = (t >= 32) ? 4 : 0;
        float s = 0.f, q = 0.f;
#pragma unroll
        for (int w2 = 0; w2 < 4; w2++) {
            s += wsum[(wb+w2)*NCH + t];
            q += wsq[(wb+w2)*NCH + t];
        }
        atomicAdd(&g_sum[0][t], (double)s);
        atomicAdd(&g_sq[0][t],  (double)q);
    }
}

// ---------------- layer 2: HMMA fp16 2-term GEMM + shfl stats ----------------
__global__ __launch_bounds__(256) void mm2_kernel(const float* __restrict__ w,
                                                  const float* __restrict__ bias)
{
    constexpr int NCH = 64;
    constexpr int ACH = 128 * 32;
    constexpr int NKC = 8;
    constexpr int ABYTES = NKC * ACH;       // 32768
    constexpr int BCH = NCH * 32;
    constexpr int BBYTES = NKC * BCH;       // 16384
    constexpr int NT8 = 4, NB4 = 2;

    extern __shared__ char dsm[];
    uint32_t raw = smem_u32(dsm);
    uint32_t abase = (raw + 1023) & ~1023u;
    char* sm  = dsm + (abase - raw);
    char* Bsm = sm + ABYTES;
    uint32_t bbase = abase + ABYTES;
    float* sh_bias = (float*)(Bsm + BBYTES);
    float* sh_sc = sh_bias + NCH;
    float* sh_sf = sh_sc + 64;

    int t = threadIdx.x;
    int wid = t >> 5, lane = t & 31;
    size_t pos0 = (size_t)blockIdx.x * 128;

    if (t < NCH) sh_bias[t] = bias[t];
    if (t < 64) { sh_sc[t] = g_scale[0][t]; sh_sf[t] = g_shift[0][t]; }
    __syncthreads();

    {
        int r = t >> 1, h = t & 1;
        uint32_t sw = SWZ(r);
        const float4* xrow = (const float4*)(g_y1 + (pos0 + r) * 64) + h * 8;
#pragma unroll
        for (int g = 0; g < 8; g++) {
            float4 v = xrow[g];
            int c = h * 32 + g * 4;
            float a0 = fmaxf(fmaf(v.x, sh_sc[c+0], sh_sf[c+0]), 0.f);
            float a1 = fmaxf(fmaf(v.y, sh_sc[c+1], sh_sf[c+1]), 0.f);
            float a2 = fmaxf(fmaf(v.z, sh_sc[c+2], sh_sf[c+2]), 0.f);
            float a3 = fmaxf(fmaf(v.w, sh_sc[c+3], sh_sf[c+3]), 0.f);
            uint32_t h01, l01, h23, l23;
            split_f16(a0, a1, h01, l01);
            split_f16(a2, a3, h23, l23);
            uint32_t off = (uint32_t)(c >> 4) * ACH + (uint32_t)r * 32
                         + ((uint32_t)((c & 15) * 2) ^ sw);
            *(uint2*)(sm + off)           = make_uint2(h01, h23);
            *(uint2*)(sm + off + 4 * ACH) = make_uint2(l01, l23);
        }
    }
    {
        int r = t >> 2, sub = t & 3;
        uint32_t sw = SWZ(r);
        const float4* wrow = (const float4*)(w + r * 64 + sub * 16);
#pragma unroll
        for (int g = 0; g < 4; g++) {
            float4 v = wrow[g];
            int c = sub * 16 + g * 4;
            uint32_t h01 = pack_f16(v.x, v.y);
            uint32_t h23 = pack_f16(v.z, v.w);
            uint32_t off = (uint32_t)(c >> 4) * BCH + (uint32_t)r * 32
                         + ((uint32_t)((c & 15) * 2) ^ sw);
            *(uint2*)(Bsm + off)           = make_uint2(h01, h23);
            *(uint2*)(Bsm + off + 4 * BCH) = make_uint2(h01, h23);
        }
    }
    __syncthreads();

    int m0 = (wid & 3) * 32;
    int n0 = (wid >> 2) * 32;

    float acc[2][NT8][4];
#pragma unroll
    for (int mi = 0; mi < 2; mi++)
#pragma unroll
        for (int nj = 0; nj < NT8; nj++)
#pragma unroll
            for (int e = 0; e < 4; e++) acc[mi][nj][e] = 0.f;

    uint32_t a_addr[2], b_addr[NB4];
#pragma unroll
    for (int mi = 0; mi < 2; mi++) {
        uint32_t row = (uint32_t)(m0 + mi*16 + (lane & 15));
        a_addr[mi] = abase + row * 32 + (((uint32_t)(lane >> 4) << 4) ^ SWZ(row));
    }
#pragma unroll
    for (int nj = 0; nj < NB4; nj++) {
        uint32_t row = (uint32_t)(n0 + nj*16 + (lane & 7) + ((lane >> 4) << 3));
        b_addr[nj] = bbase + row * 32 + ((((uint32_t)(lane >> 3) & 1u) << 4) ^ SWZ(row));
    }

#pragma unroll
    for (int kc = 0; kc < NKC; kc++) {
        uint32_t af[2][4];
        ldm4(a_addr[0] + kc * ACH, af[0]);
        ldm4(a_addr[1] + kc * ACH, af[1]);
        uint32_t bf[NT8][2];
#pragma unroll
        for (int nj = 0; nj < NB4; nj++) {
            uint32_t tmp[4];
            ldm4(b_addr[nj] + kc * BCH, tmp);
            bf[2*nj][0] = tmp[0]; bf[2*nj][1] = tmp[1];
            bf[2*nj+1][0] = tmp[2]; bf[2*nj+1][1] = tmp[3];
        }
#pragma unroll
        for (int mi = 0; mi < 2; mi++)
#pragma unroll
            for (int nj = 0; nj < NT8; nj++)
                mma_f16(acc[mi][nj], af[mi], bf[nj]);
    }

    int rq = lane >> 2, cq = (lane & 3) * 2;
    float ps[2*NT8], pq[2*NT8];
#pragma unroll
    for (int nj = 0; nj < NT8; nj++) {
        int col = n0 + nj*8 + cq;
        float b0 = sh_bias[col], b1 = sh_bias[col+1];
        float y00 = acc[0][nj][0] + b0, y01 = acc[0][nj][1] + b1;
        float y10 = acc[0][nj][2] + b0, y11 = acc[0][nj][3] + b1;
        float y20 = acc[1][nj][0] + b0, y21 = acc[1][nj][1] + b1;
        float y30 = acc[1][nj][2] + b0, y31 = acc[1][nj][3] + b1;
        size_t r0 = pos0 + m0 + rq;
        *(float2*)(g_y2 + r0 * 64 + col)        = make_float2(y00, y01);
        *(float2*)(g_y2 + (r0 + 8) * 64 + col)  = make_float2(y10, y11);
        *(float2*)(g_y2 + (r0 + 16) * 64 + col) = make_float2(y20, y21);
        *(float2*)(g_y2 + (r0 + 24) * 64 + col) = make_float2(y30, y31);
        ps[2*nj]   = y00 + y10 + y20 + y30;
        ps[2*nj+1] = y01 + y11 + y21 + y31;
        pq[2*nj]   = y00*y00 + y10*y10 + y20*y20 + y30*y30;
        pq[2*nj+1] = y01*y01 + y11*y11 + y21*y21 + y31*y31;
    }
    RQ_REDUCE(ps, 2*NT8);
    RQ_REDUCE(pq, 2*NT8);
    __syncthreads();
    float* wsum = (float*)sm;
    float* wsq  = wsum + 8 * NCH;
    if (lane < 4) {
#pragma unroll
        for (int nj = 0; nj < NT8; nj++) {
            int col = n0 + nj*8 + cq;
            wsum[wid*NCH + col]   = ps[2*nj];
            wsum[wid*NCH + col+1] = ps[2*nj+1];
            wsq[wid*NCH + col]    = pq[2*nj];
            wsq[wid*NCH + col+1]  = pq[2*nj+1];
        }
    }
    __syncthreads();
    if (t < NCH) {
        int wb = (t >= 32) ? 4 : 0;
        float s = 0.f, q = 0.f;
#pragma unroll
        for (int w2 = 0; w2 < 4; w2++) {
            s += wsum[(wb+w2)*NCH + t];
            q += wsq[(wb+w2)*NCH + t];
        }
        atomicAdd(&g_sum[1][t], (double)s);
        atomicAdd(&g_sq[1][t],  (double)q);
    }
}

// ---------------- layer 3: HMMA fp16 GEMM + shfl stats + per-query max/min ---
__global__ __launch_bounds__(256) void mm3_kernel(const float* __restrict__ w,
                                                  const float* __restrict__ bias)
{
    constexpr int NCH = 128;
    constexpr int ACH = 128 * 32;
    constexpr int NKC = 8;
    constexpr int ABYTES = NKC * ACH;       // 32768
    constexpr int BCH = NCH * 32;
    constexpr int BBYTES = NKC * BCH;       // 32768
    constexpr int NT8 = 8, NB4 = 4;

    extern __shared__ char dsm[];
    uint32_t raw = smem_u32(dsm);
    uint32_t abase = (raw + 1023) & ~1023u;
    char* sm  = dsm + (abase - raw);
    char* Bsm = sm + ABYTES;
    uint32_t bbase = abase + ABYTES;
    float* sh_bias = (float*)(Bsm + BBYTES);
    float* sh_sc = sh_bias + NCH;
    float* sh_sf = sh_sc + 64;

    int t = threadIdx.x;
    int wid = t >> 5, lane = t & 31;
    size_t pos0 = (size_t)blockIdx.x * 128;

    if (t < NCH) sh_bias[t] = bias[t];
    if (t < 64) { sh_sc[t] = g_scale[1][t]; sh_sf[t] = g_shift[1][t]; }
    __syncthreads();

    {
        int r = t >> 1, h = t & 1;
        uint32_t sw = SWZ(r);
        const float4* xrow = (const float4*)(g_y2 + (pos0 + r) * 64) + h * 8;
#pragma unroll
        for (int g = 0; g < 8; g++) {
            float4 v = xrow[g];
            int c = h * 32 + g * 4;
            float a0 = fmaxf(fmaf(v.x, sh_sc[c+0], sh_sf[c+0]), 0.f);
            float a1 = fmaxf(fmaf(v.y, sh_sc[c+1], sh_sf[c+1]), 0.f);
            float a2 = fmaxf(fmaf(v.z, sh_sc[c+2], sh_sf[c+2]), 0.f);
            float a3 = fmaxf(fmaf(v.w, sh_sc[c+3], sh_sf[c+3]), 0.f);
            uint32_t h01, l01, h23, l23;
            split_f16(a0, a1, h01, l01);
            split_f16(a2, a3, h23, l23);
            uint32_t off = (uint32_t)(c >> 4) * ACH + (uint32_t)r * 32
                         + ((uint32_t)((c & 15) * 2) ^ sw);
            *(uint2*)(sm + off)           = make_uint2(h01, h23);
            *(uint2*)(sm + off + 4 * ACH) = make_uint2(l01, l23);
        }
    }
    {
        int r = t >> 1, sub = t & 1;
        uint32_t sw = SWZ(r);
        const float4* wrow = (const float4*)(w + r * 64 + sub * 32);
#pragma unroll
        for (int g = 0; g < 8; g++) {
            float4 v = wrow[g];
            int c = sub * 32 + g * 4;
            uint32_t h01 = pack_f16(v.x, v.y);
            uint32_t h23 = pack_f16(v.z, v.w);
            uint32_t off = (uint32_t)(c >> 4) * BCH + (uint32_t)r * 32
                         + ((uint32_t)((c & 15) * 2) ^ sw);
            *(uint2*)(Bsm + off)           = make_uint2(h01, h23);
            *(uint2*)(Bsm + off + 4 * BCH) = make_uint2(h01, h23);
        }
    }
    __syncthreads();

    int m0 = (wid & 3) * 32;
    int n0 = (wid >> 2) * 64;

    float acc[2][NT8][4];
#pragma unroll
    for (int mi = 0; mi < 2; mi++)
#pragma unroll
        for (int nj = 0; nj < NT8; nj++)
#pragma unroll
            for (int e = 0; e < 4; e++) acc[mi][nj][e] = 0.f;

    uint32_t a_addr[2], b_addr[NB4];
#pragma unroll
    for (int mi = 0; mi < 2; mi++) {
        uint32_t row = (uint32_t)(m0 + mi*16 + (lane & 15));
        a_addr[mi] = abase + row * 32 + (((uint32_t)(lane >> 4) << 4) ^ SWZ(row));
    }
#pragma unroll
    for (int nj = 0; nj < NB4; nj++) {
        uint32_t row = (uint32_t)(n0 + nj*16 + (lane & 7) + ((lane >> 4) << 3));
        b_addr[nj] = bbase + row * 32 + ((((uint32_t)(lane >> 3) & 1u) << 4) ^ SWZ(row));
    }

#pragma unroll
    for (int kc = 0; kc < NKC; kc++) {
        uint32_t af[2][4];
        ldm4(a_addr[0] + kc * ACH, af[0]);
        ldm4(a_addr[1] + kc * ACH, af[1]);
        uint32_t bf[NT8][2];
#pragma unroll
        for (int nj = 0; nj < NB4; nj++) {
            uint32_t tmp[4];
            ldm4(b_addr[nj] + kc * BCH, tmp);
            bf[2*nj][0] = tmp[0]; bf[2*nj][1] = tmp[1];
            bf[2*nj+1][0] = tmp[2]; bf[2*nj+1][1] = tmp[3];
        }
#pragma unroll
        for (int mi = 0; mi < 2; mi++)
#pragma unroll
            for (int nj = 0; nj < NT8; nj++)
                mma_f16(acc[mi][nj], af[mi], bf[nj]);
    }

    // ---- epilogue: bias, shfl stats, per-query max/min (no global y3) ----
    int rq = lane >> 2, cq = (lane & 3) * 2;
    int q = wid & 3;
    float ps[2*NT8], pq[2*NT8];
    float tmax[NT8][2], tmin[NT8][2];
#pragma unroll
    for (int nj = 0; nj < NT8; nj++) {
        int col = n0 + nj*8 + cq;
        float b0 = sh_bias[col], b1 = sh_bias[col+1];
        float y00 = acc[0][nj][0] + b0, y01 = acc[0][nj][1] + b1;
        float y10 = acc[0][nj][2] + b0, y11 = acc[0][nj][3] + b1;
        float y20 = acc[1][nj][0] + b0, y21 = acc[1][nj][1] + b1;
        float y30 = acc[1][nj][2] + b0, y31 = acc[1][nj][3] + b1;
        tmax[nj][0] = fmaxf(fmaxf(y00, y10), fmaxf(y20, y30));
        tmax[nj][1] = fmaxf(fmaxf(y01, y11), fmaxf(y21, y31));
        tmin[nj][0] = fminf(fminf(y00, y10), fminf(y20, y30));
        tmin[nj][1] = fminf(fminf(y01, y11), fminf(y21, y31));
        ps[2*nj]   = y00 + y10 + y20 + y30;
        ps[2*nj+1] = y01 + y11 + y21 + y31;
        pq[2*nj]   = y00*y00 + y10*y10 + y20*y20 + y30*y30;
        pq[2*nj+1] = y01*y01 + y11*y11 + y21*y21 + y31*y31;
    }
    RQ_REDUCE(ps, 2*NT8);
    RQ_REDUCE(pq, 2*NT8);
    __syncthreads();              // all A/B smem reads complete; reuse regions

    float* shmx = (float*)sm;                    // 16 KB: [q*8+rq][128]
    float* shmn = (float*)(sm + 16384);          // 16 KB
    float* wsum = (float*)(sm + 32768);          // 4 KB (B region): [8][128]
    float* wsq  = (float*)(sm + 36864);          // 4 KB
#pragma unroll
    for (int nj = 0; nj < NT8; nj++) {
        int col = n0 + nj*8 + cq;
        int idx = (q * 8 + rq) * 128 + col;
        *(float2*)&shmx[idx] = make_float2(tmax[nj][0], tmax[nj][1]);
        *(float2*)&shmn[idx] = make_float2(tmin[nj][0], tmin[nj][1]);
    }
    if (lane < 4) {
#pragma unroll
        for (int nj = 0; nj < NT8; nj++) {
            int col = n0 + nj*8 + cq;
            wsum[wid*NCH + col]   = ps[2*nj];
            wsum[wid*NCH + col+1] = ps[2*nj+1];
            wsq[wid*NCH + col]    = pq[2*nj];
            wsq[wid*NCH + col+1]  = pq[2*nj+1];
        }
    }
    __syncthreads();

    if (t < 128) {
        int wb = (t >= 64) ? 4 : 0;
        float s = 0.f, qq = 0.f;
#pragma unroll
        for (int w2 = 0; w2 < 4; w2++) {
            s += wsum[(wb+w2)*NCH + t];
            qq += wsq[(wb+w2)*NCH + t];
        }
        atomicAdd(&g_sum[2][t], (double)s);
        atomicAdd(&g_sq[2][t],  (double)qq);
    }
#pragma unroll
    for (int u = t; u < 512; u += 256) {
        int uq = u >> 7, col = u & 127;
        float m = shmx[(uq * 8) * 128 + col];
        float n = shmn[(uq * 8) * 128 + col];
#pragma unroll
        for (int p = 1; p < 8; p++) {
            m = fmaxf(m, shmx[(uq * 8 + p) * 128 + col]);
            n = fminf(n, shmn[(uq * 8 + p) * 128 + col]);
        }
        size_t gq = (size_t)blockIdx.x * 4 + uq;
        g_mx[(size_t)col * QTOT + gq] = m;
        g_mn[(size_t)col * QTOT + gq] = n;
    }
}

// ---------------- final: affine+relu on (max,min), coalesced -----------------
__global__ void final_kernel(float* __restrict__ out) {
    int ch = blockIdx.x >> 6;
    int q  = ((blockIdx.x & 63) << 8) + threadIdx.x;
    float sc = g_scale[2][ch], sh = g_shift[2][ch];
    float mx = g_mx[(size_t)ch * QTOT + q];
    float mn = g_mn[(size_t)ch * QTOT + q];
    float v = fmaxf(fmaxf(fmaf(sc, mx, sh), fmaf(sc, mn, sh)), 0.f);
    int b = q >> 10, s = q & 1023;
    out[OUT_OFF + ((size_t)b * 128 + ch) * SS + s] = v;
}

// ---------------- launcher ----------------------------------------------------
extern "C" void kernel_launch(void* const* d_in, const int* in_sizes, int n_in,
                              void* d_out, int out_size) {
    (void)in_sizes; (void)n_in; (void)out_size;
    const float* xyz    = (const float*)d_in[0];
    const float* points = (const float*)d_in[1];
    const float* w1  = (const float*)d_in[2];
    const float* b1  = (const float*)d_in[3];
    const float* g1  = (const float*)d_in[4];
    const float* be1 = (const float*)d_in[5];
    const float* w2  = (const float*)d_in[6];
    const float* b2  = (const float*)d_in[7];
    const float* g2  = (const float*)d_in[8];
    const float* be2 = (const float*)d_in[9];
    const float* w3  = (const float*)d_in[10];
    const float* b3  = (const float*)d_in[11];
    const float* g3  = (const float*)d_in[12];
    const float* be3 = (const float*)d_in[13];
    float* out = (float*)d_out;

    const int DYN1 = 1024 + 40960 + 20480 + 1024;   // 63488
    const int DYN2 = 1024 + 32768 + 16384 + 2048;   // 52224
    const int DYN3 = 1024 + 32768 + 32768 + 2048;   // 68608
    cudaFuncSetAttribute(mm1_kernel, cudaFuncAttributeMaxDynamicSharedMemorySize, DYN1);
    cudaFuncSetAttribute(mm2_kernel, cudaFuncAttributeMaxDynamicSharedMemorySize, DYN2);
    cudaFuncSetAttribute(mm3_kernel, cudaFuncAttributeMaxDynamicSharedMemorySize, DYN3);

    init_kernel<<<1, 512>>>();
    fps_kernel<<<BB, 1024>>>(xyz);
    gather_newxyz_kernel<<<(QTOT + 255) / 256, 256>>>(xyz, out);
    qb_kernel<<<(QTOT) / 8, 256>>>(xyz);

    mm1_kernel<<<MTOT / 128, 256, DYN1>>>(xyz, points, out, w1, b1);
    stats_kernel<<<1, 128>>>(0, g1, be1, 64);

    mm2_kernel<<<MTOT / 128, 256, DYN2>>>(w2, b2);
    stats_kernel<<<1, 128>>>(1, g2, be2, 64);

    mm3_kernel<<<MTOT / 128, 256, DYN3>>>(w3, b3);
    stats_kernel<<<1, 128>>>(2, g3, be3, 128);

    final_kernel<<<128 * 64, 256>>>(out);
}

// round 15
// speedup vs baseline: 1.5791x; 1.5791x over previous
#include <cuda_runtime.h>
#include <cuda_bf16.h>
#include <cstdint>
#include <cstddef>

#define BB 16
#define NN 8192
#define SS 1024
#define KK 32
#define R2C 0.04f          /* float(0.2**2) */
#define EPSC 1e-5f
#define MTOT (BB*SS*KK)    /* 524288 positions */
#define QTOT (BB*SS)       /* 16384 queries */
#define OUT_OFF (BB*SS*3)

typedef unsigned long long ull;

// ---------------- packed f32x2 helpers ----------------------------------------
__device__ __forceinline__ ull fma2(ull a, ull b, ull c) {
    ull d; asm("fma.rn.f32x2 %0,%1,%2,%3;" : "=l"(d) : "l"(a), "l"(b), "l"(c)); return d;
}
__device__ __forceinline__ ull mul2(ull a, ull b) {
    ull d; asm("mul.rn.f32x2 %0,%1,%2;" : "=l"(d) : "l"(a), "l"(b)); return d;
}
__device__ __forceinline__ ull add2(ull a, ull b) {
    ull d; asm("add.rn.f32x2 %0,%1,%2;" : "=l"(d) : "l"(a), "l"(b)); return d;
}
__device__ __forceinline__ ull dup2(float x) {
    ull d; asm("mov.b64 %0,{%1,%1};" : "=l"(d) : "f"(x)); return d;
}
__device__ __forceinline__ ull pk2(float lo, float hi) {
    ull d; asm("mov.b64 %0,{%1,%2};" : "=l"(d) : "f"(lo), "f"(hi)); return d;
}
__device__ __forceinline__ float2 up2(ull v) {
    float2 r; asm("mov.b64 {%0,%1},%2;" : "=f"(r.x), "=f"(r.y) : "l"(v)); return r;
}

// ---------------- HMMA / ldmatrix helpers (baseline PTX, sm_103-safe) ---------
__device__ __forceinline__ uint32_t smem_u32(const void* p) {
    uint32_t a;
    asm("{ .reg .u64 t; cvta.to.shared.u64 t, %1; cvt.u32.u64 %0, t; }" : "=r"(a) : "l"(p));
    return a;
}
__device__ __forceinline__ void ldm4(uint32_t addr, uint32_t* r) {
    asm volatile("ldmatrix.sync.aligned.m8n8.x4.shared.b16 {%0,%1,%2,%3}, [%4];"
                 : "=r"(r[0]), "=r"(r[1]), "=r"(r[2]), "=r"(r[3]) : "r"(addr));
}
__device__ __forceinline__ void mma_f16(float* c, const uint32_t* a, const uint32_t* b) {
    asm volatile(
        "mma.sync.aligned.m16n8k16.row.col.f32.f16.f16.f32 "
        "{%0,%1,%2,%3}, {%4,%5,%6,%7}, {%8,%9}, {%0,%1,%2,%3};"
        : "+f"(c[0]), "+f"(c[1]), "+f"(c[2]), "+f"(c[3])
        : "r"(a[0]), "r"(a[1]), "r"(a[2]), "r"(a[3]), "r"(b[0]), "r"(b[1]));
}

// split fp32 pair -> packed fp16 highs + packed fp16 residuals (a ~= ah + al)
__device__ __forceinline__ void split_f16(float a, float b, uint32_t& hi, uint32_t& lo) {
    asm("{.reg .b16 ha,hb,la,lb;\n"
        " .reg .f32 fa,fb;\n"
        " cvt.rn.f16.f32 ha, %2;\n"
        " cvt.rn.f16.f32 hb, %3;\n"
        " cvt.f32.f16 fa, ha;\n"
        " cvt.f32.f16 fb, hb;\n"
        " sub.f32 fa, %2, fa;\n"
        " sub.f32 fb, %3, fb;\n"
        " cvt.rn.f16.f32 la, fa;\n"
        " cvt.rn.f16.f32 lb, fb;\n"
        " mov.b32 %0, {ha,hb};\n"
        " mov.b32 %1, {la,lb};}"
        : "=r"(hi), "=r"(lo) : "f"(a), "f"(b));
}
__device__ __forceinline__ uint32_t pack_f16(float a, float b) {
    uint32_t r;
    asm("{.reg .b16 x,y; cvt.rn.f16.f32 x,%1; cvt.rn.f16.f32 y,%2; mov.b32 %0,{x,y};}"
        : "=r"(r) : "f"(a), "f"(b));
    return r;
}

// ---------------- device scratch ----------------------------------------------
__device__ int    g_fps[QTOT];
__device__ int    g_idx[(size_t)QTOT*KK];
__device__ float  g_y1[(size_t)MTOT*64];
__device__ float  g_y2[(size_t)MTOT*64];
__device__ float  g_mx[(size_t)128*QTOT];   // [ch][q]
__device__ float  g_mn[(size_t)128*QTOT];
__device__ double g_sum[3][128];
__device__ double g_sq[3][128];
__device__ float  g_scale[3][128];
__device__ float  g_shift[3][128];

// ---------------- init --------------------------------------------------------
__global__ void init_kernel() {
    int t = blockIdx.x * blockDim.x + threadIdx.x;
    if (t < 3 * 128) {
        ((double*)g_sum)[t] = 0.0;
        ((double*)g_sq)[t]  = 0.0;
    }
}

// ---------------- farthest point sampling: 1 barrier/iter --------------------
__global__ __launch_bounds__(1024) void fps_kernel(const float* __restrict__ xyz) {
    int b = blockIdx.x;
    int t = threadIdx.x;
    int lane = t & 31, w = t >> 5;
    const float* xb = xyz + (size_t)b * NN * 3;

    ull px2[4], py2[4], pz2[4];
    float dist[8];
#pragma unroll
    for (int j = 0; j < 4; j++) {
        int p0 = t + (2*j)   * 1024;
        int p1 = t + (2*j+1) * 1024;
        px2[j] = pk2(xb[p0*3+0], xb[p1*3+0]);
        py2[j] = pk2(xb[p0*3+1], xb[p1*3+1]);
        pz2[j] = pk2(xb[p0*3+2], xb[p1*3+2]);
    }
#pragma unroll
    for (int i = 0; i < 8; i++) dist[i] = 1e10f;

    __shared__ ull s_key[2][32];
    int far = 0;
    int buf = 0;

    for (int it = 0; it < SS; it++) {
        if (t == 0) g_fps[b * SS + it] = far;
        float cx = xb[far*3+0], cy = xb[far*3+1], cz = xb[far*3+2];
        ull ncx = dup2(-cx), ncy = dup2(-cy), ncz = dup2(-cz);

        float bestv = -1.0f; int besti = 0;
#pragma unroll
        for (int j = 0; j < 4; j++) {
            ull dx = add2(px2[j], ncx);
            ull dy = add2(py2[j], ncy);
            ull dz = add2(pz2[j], ncz);
            ull d2 = mul2(dx, dx);
            d2 = fma2(dy, dy, d2);
            d2 = fma2(dz, dz, d2);
            float2 dd = up2(d2);
            float n0 = fminf(dist[2*j],   dd.x);
            float n1 = fminf(dist[2*j+1], dd.y);
            dist[2*j] = n0; dist[2*j+1] = n1;
            if (n0 > bestv) { bestv = n0; besti = t + (2*j)   * 1024; }
            if (n1 > bestv) { bestv = n1; besti = t + (2*j+1) * 1024; }
        }

        unsigned bits = __float_as_uint(bestv);
        unsigned mh = __reduce_max_sync(0xffffffffu, bits);
        unsigned ml = __reduce_max_sync(0xffffffffu, (bits == mh) ? ~(unsigned)besti : 0u);
        if (lane == 0) s_key[buf][w] = ((ull)mh << 32) | ml;
        __syncthreads();
        ull k = s_key[buf][lane];
        unsigned h2 = (unsigned)(k >> 32);
        unsigned m2 = __reduce_max_sync(0xffffffffu, h2);
        unsigned l2 = __reduce_max_sync(0xffffffffu, (h2 == m2) ? (unsigned)k : 0u);
        far = (int)(~l2);
        buf ^= 1;
    }
}

// ---------------- gather new_xyz into output ---------------------------------
__global__ void gather_newxyz_kernel(const float* __restrict__ xyz,
                                     float* __restrict__ out) {
    int i = blockIdx.x * blockDim.x + threadIdx.x;
    if (i < QTOT) {
        int b = i >> 10;
        int j = g_fps[i];
        const float* p = xyz + ((size_t)b * NN + j) * 3;
        out[i*3+0] = p[0];
        out[i*3+1] = p[1];
        out[i*3+2] = p[2];
    }
}

// ---------------- ball query: one warp per query, 1-deep prefetch ------------
__global__ void qb_kernel(const float* __restrict__ xyz) {
    int q = (blockIdx.x * blockDim.x + threadIdx.x) >> 5;
    int lane = threadIdx.x & 31;
    int b = q >> 10;
    const float* xb = xyz + (size_t)b * NN * 3;
    int c = g_fps[q];
    float cx = xb[c*3+0], cy = xb[c*3+1], cz = xb[c*3+2];

    int cnt = 0;
    int first = 0;
    bool have_first = false;
    int* out = g_idx + (size_t)q * KK;

    int p = lane;
    float x = xb[p*3+0], y = xb[p*3+1], z = xb[p*3+2];

    for (int base = 0; base < NN; base += 32) {
        float nx = 0.f, ny = 0.f, nz = 0.f;
        if (base + 32 < NN) {
            int pn = base + 32 + lane;
            nx = xb[pn*3+0]; ny = xb[pn*3+1]; nz = xb[pn*3+2];
        }
        float dx = x - cx, dy = y - cy, dz = z - cz;
        float d = dx*dx + dy*dy + dz*dz;
        bool in = (d <= R2C);
        unsigned m = __ballot_sync(0xffffffffu, in);
        if (m) {
            int pos = cnt + __popc(m & ((1u << lane) - 1u));
            if (in && pos < KK) out[pos] = p;
            if (!have_first) { first = base + __ffs(m) - 1; have_first = true; }
            cnt += __popc(m);
            if (cnt >= KK) break;
        }
        p = base + 32 + lane; x = nx; y = ny; z = nz;
    }
    for (int pos = cnt + lane; pos < KK; pos += 32) out[pos] = first;
}

// ---------------- per-channel BN fold ----------------------------------------
__global__ void stats_kernel(int L, const float* __restrict__ gam,
                             const float* __restrict__ bet, int C) {
    int t = threadIdx.x;
    if (t < C) {
        double mean = g_sum[L][t] * (1.0 / (double)MTOT);
        double var  = g_sq[L][t]  * (1.0 / (double)MTOT) - mean * mean;
        float sc = gam[t] * rsqrtf((float)var + EPSC);
        g_scale[L][t] = sc;
        g_shift[L][t] = fmaf(-(float)mean, sc, bet[t]);
    }
}

// shfl butterfly over the 8 rq-lanes (xor 4, 8, 16)
#define RQ_REDUCE(arr, cnt)                                             \
    _Pragma("unroll")                                                   \
    for (int _mask = 4; _mask <= 16; _mask <<= 1)                       \
        _Pragma("unroll")                                               \
        for (int _i = 0; _i < (cnt); _i++)                              \
            (arr)[_i] += __shfl_xor_sync(0xffffffffu, (arr)[_i], _mask);

// bank-conflict swizzle: flip the 16B half with row bit 2
#define SWZ(r) ((((uint32_t)(r) >> 2) & 1u) << 4)

// ---------------- layer 1: HMMA gather-GEMM (K=67 pad 80 -> 64) + stats ------
// fp16 2-term split: A' = [ah(80) | al(80)]; B single copy, indexed kc%5.
// k-channel order: 0..63 = points, 64..66 = xyz-norm, 67..79 = zero pad.
__global__ __launch_bounds__(256) void mm1_kernel(
    const float* __restrict__ xyz, const float* __restrict__ points,
    const float* __restrict__ newxyz,
    const float* __restrict__ w, const float* __restrict__ bias)
{
    constexpr int NCH = 64;
    constexpr int ACH = 128 * 32;           // 4096 B per A k-chunk
    constexpr int NKC = 10;                 // A chunks (5 ah + 5 al)
    constexpr int NKB = 5;                  // B chunks (single copy)
    constexpr int ABYTES = NKC * ACH;       // 40960
    constexpr int BCH = NCH * 32;           // 2048
    constexpr int BBYTES = NKB * BCH;       // 10240
    constexpr int NT8 = 4, NB4 = 2;

    extern __shared__ char dsm[];
    uint32_t raw = smem_u32(dsm);
    uint32_t abase = (raw + 1023) & ~1023u;
    char* sm  = dsm + (abase - raw);
    char* Bsm = sm + ABYTES;
    uint32_t bbase = abase + ABYTES;
    float* sh_bias = (float*)(Bsm + BBYTES);

    int t = threadIdx.x;
    int wid = t >> 5, lane = t & 31;
    size_t pos0 = (size_t)blockIdx.x * 128;

    if (t < NCH) sh_bias[t] = bias[t];

    // ---- stage A: 2 threads per row ----
    {
        int r = t >> 1, h = t & 1;
        size_t pos = pos0 + r;
        int j = g_idx[pos];
        int b = (int)(pos >> 15);
        int s = (int)((pos >> 5) & 1023);
        uint32_t sw = SWZ(r);
        const float4* prow = (const float4*)(points + ((size_t)b * NN + j) * 64) + h * 8;
#pragma unroll
        for (int g = 0; g < 8; g++) {
            float4 v = prow[g];
            int c = h * 32 + g * 4;
            uint32_t h01, l01, h23, l23;
            split_f16(v.x, v.y, h01, l01);
            split_f16(v.z, v.w, h23, l23);
            uint32_t off = (uint32_t)(c >> 4) * ACH + (uint32_t)r * 32
                         + ((uint32_t)((c & 15) * 2) ^ sw);
            *(uint2*)(sm + off)           = make_uint2(h01, h23);   // ah
            *(uint2*)(sm + off + 5 * ACH) = make_uint2(l01, l23);   // al
        }
        if (!h) {
            const float* xr = xyz + ((size_t)b * NN + j) * 3;
            const float* nr = newxyz + ((size_t)b * SS + s) * 3;
            float x0 = xr[0] - nr[0], x1 = xr[1] - nr[1], x2 = xr[2] - nr[2];
            uint32_t h01, l01, h23, l23;
            split_f16(x0, x1, h01, l01);
            split_f16(x2, 0.f, h23, l23);
            uint32_t base = 4 * ACH + (uint32_t)r * 32;
            uint2 z = make_uint2(0u, 0u);
            *(uint2*)(sm + base + (0u ^ sw))            = make_uint2(h01, h23);
            *(uint2*)(sm + base + (8u ^ sw))            = z;
            *(uint2*)(sm + base + (16u ^ sw))           = z;
            *(uint2*)(sm + base + (24u ^ sw))           = z;
            *(uint2*)(sm + base + 5*ACH + (0u ^ sw))    = make_uint2(l01, l23);
            *(uint2*)(sm + base + 5*ACH + (8u ^ sw))    = z;
            *(uint2*)(sm + base + 5*ACH + (16u ^ sw))   = z;
            *(uint2*)(sm + base + 5*ACH + (24u ^ sw))   = z;
        }
    }
    // ---- stage B: w1 rows, permuted channels, single fp16 copy ----
    {
        int r = t >> 2, sub = t & 3;
        uint32_t sw = SWZ(r);
        const float* wr = w + r * 67;
#pragma unroll
        for (int g = 0; g < 5; g++) {
            int kq = sub * 20 + g * 4;
            float v[4];
#pragma unroll
            for (int i = 0; i < 4; i++) {
                int kc = kq + i;
                v[i] = (kc < 64) ? wr[3 + kc] : ((kc < 67) ? wr[kc - 64] : 0.f);
            }
            uint32_t h01 = pack_f16(v[0], v[1]);
            uint32_t h23 = pack_f16(v[2], v[3]);
            uint32_t off = (uint32_t)(kq >> 4) * BCH + (uint32_t)r * 32
                         + ((uint32_t)((kq & 15) * 2) ^ sw);
            *(uint2*)(Bsm + off) = make_uint2(h01, h23);
        }
    }
    __syncthreads();

    int m0 = (wid & 3) * 32;
    int n0 = (wid >> 2) * 32;

    float acc[2][NT8][4];
#pragma unroll
    for (int mi = 0; mi < 2; mi++)
#pragma unroll
        for (int nj = 0; nj < NT8; nj++)
#pragma unroll
            for (int e = 0; e < 4; e++) acc[mi][nj][e] = 0.f;

    uint32_t a_addr[2], b_addr[NB4];
#pragma unroll
    for (int mi = 0; mi < 2; mi++) {
        uint32_t row = (uint32_t)(m0 + mi*16 + (lane & 15));
        a_addr[mi] = abase + row * 32 + (((uint32_t)(lane >> 4) << 4) ^ SWZ(row));
    }
#pragma unroll
    for (int nj = 0; nj < NB4; nj++) {
        uint32_t row = (uint32_t)(n0 + nj*16 + (lane & 7) + ((lane >> 4) << 3));
        b_addr[nj] = bbase + row * 32 + ((((uint32_t)(lane >> 3) & 1u) << 4) ^ SWZ(row));
    }

#pragma unroll
    for (int kc = 0; kc < NKC; kc++) {
        int bkc = (kc < NKB) ? kc : kc - NKB;
        uint32_t af[2][4];
        ldm4(a_addr[0] + kc * ACH, af[0]);
        ldm4(a_addr[1] + kc * ACH, af[1]);
        uint32_t bf[NT8][2];
#pragma unroll
        for (int nj = 0; nj < NB4; nj++) {
            uint32_t tmp[4];
            ldm4(b_addr[nj] + bkc * BCH, tmp);
            bf[2*nj][0] = tmp[0]; bf[2*nj][1] = tmp[1];
            bf[2*nj+1][0] = tmp[2]; bf[2*nj+1][1] = tmp[3];
        }
#pragma unroll
        for (int mi = 0; mi < 2; mi++)
#pragma unroll
            for (int nj = 0; nj < NT8; nj++)
                mma_f16(acc[mi][nj], af[mi], bf[nj]);
    }

    // ---- epilogue: bias + store + shfl-reduced stats ----
    int rq = lane >> 2, cq = (lane & 3) * 2;
    float ps[2*NT8], pq[2*NT8];
#pragma unroll
    for (int nj = 0; nj < NT8; nj++) {
        int col = n0 + nj*8 + cq;
        float b0 = sh_bias[col], b1 = sh_bias[col+1];
        float y00 = acc[0][nj][0] + b0, y01 = acc[0][nj][1] + b1;
        float y10 = acc[0][nj][2] + b0, y11 = acc[0][nj][3] + b1;
        float y20 = acc[1][nj][0] + b0, y21 = acc[1][nj][1] + b1;
        float y30 = acc[1][nj][2] + b0, y31 = acc[1][nj][3] + b1;
        size_t r0 = pos0 + m0 + rq;
        *(float2*)(g_y1 + r0 * 64 + col)        = make_float2(y00, y01);
        *(float2*)(g_y1 + (r0 + 8) * 64 + col)  = make_float2(y10, y11);
        *(float2*)(g_y1 + (r0 + 16) * 64 + col) = make_float2(y20, y21);
        *(float2*)(g_y1 + (r0 + 24) * 64 + col) = make_float2(y30, y31);
        ps[2*nj]   = y00 + y10 + y20 + y30;
        ps[2*nj+1] = y01 + y11 + y21 + y31;
        pq[2*nj]   = y00*y00 + y10*y10 + y20*y20 + y30*y30;
        pq[2*nj+1] = y01*y01 + y11*y11 + y21*y21 + y31*y31;
    }
    RQ_REDUCE(ps, 2*NT8);
    RQ_REDUCE(pq, 2*NT8);
    __syncthreads();
    float* wsum = (float*)sm;              // [8][NCH]
    float* wsq  = wsum + 8 * NCH;
    if (lane < 4) {
#pragma unroll
        for (int nj = 0; nj < NT8; nj++) {
            int col = n0 + nj*8 + cq;
            wsum[wid*NCH + col]   = ps[2*nj];
            wsum[wid*NCH + col+1] = ps[2*nj+1];
            wsq[wid*NCH + col]    = pq[2*nj];
            wsq[wid*NCH + col+1]  = pq[2*nj+1];
        }
    }
    __syncthreads();
    if (t < NCH) {
        int wb = (t >= 32) ? 4 : 0;
        float s = 0.f, q = 0.f;
#pragma unroll
        for (int w2 = 0; w2 < 4; w2++) {
            s += wsum[(wb+w2)*NCH + t];
            q += wsq[(wb+w2)*NCH + t];
        }
        atomicAdd(&g_sum[0][t], (double)s);
        atomicAdd(&g_sq[0][t],  (double)q);
    }
}

// ---------------- layer 2: HMMA fp16 2-term GEMM + shfl stats ----------------
__global__ __launch_bounds__(256) void mm2_kernel(const float* __restrict__ w,
                                                  const float* __restrict__ bias)
{
    constexpr int NCH = 64;
    constexpr int ACH = 128 * 32;
    constexpr int NKC = 8;                  // A chunks (4 ah + 4 al)
    constexpr int NKB = 4;                  // B chunks (single copy)
    constexpr int ABYTES = NKC * ACH;       // 32768
    constexpr int BCH = NCH * 32;
    constexpr int BBYTES = NKB * BCH;       // 8192
    constexpr int NT8 = 4, NB4 = 2;

    extern __shared__ char dsm[];
    uint32_t raw = smem_u32(dsm);
    uint32_t abase = (raw + 1023) & ~1023u;
    char* sm  = dsm + (abase - raw);
    char* Bsm = sm + ABYTES;
    uint32_t bbase = abase + ABYTES;
    float* sh_bias = (float*)(Bsm + BBYTES);
    float* sh_sc = sh_bias + NCH;
    float* sh_sf = sh_sc + 64;

    int t = threadIdx.x;
    int wid = t >> 5, lane = t & 31;
    size_t pos0 = (size_t)blockIdx.x * 128;

    if (t < NCH) sh_bias[t] = bias[t];
    if (t < 64) { sh_sc[t] = g_scale[0][t]; sh_sf[t] = g_shift[0][t]; }
    __syncthreads();

    {
        int r = t >> 1, h = t & 1;
        uint32_t sw = SWZ(r);
        const float4* xrow = (const float4*)(g_y1 + (pos0 + r) * 64) + h * 8;
#pragma unroll
        for (int g = 0; g < 8; g++) {
            float4 v = xrow[g];
            int c = h * 32 + g * 4;
            float a0 = fmaxf(fmaf(v.x, sh_sc[c+0], sh_sf[c+0]), 0.f);
            float a1 = fmaxf(fmaf(v.y, sh_sc[c+1], sh_sf[c+1]), 0.f);
            float a2 = fmaxf(fmaf(v.z, sh_sc[c+2], sh_sf[c+2]), 0.f);
            float a3 = fmaxf(fmaf(v.w, sh_sc[c+3], sh_sf[c+3]), 0.f);
            uint32_t h01, l01, h23, l23;
            split_f16(a0, a1, h01, l01);
            split_f16(a2, a3, h23, l23);
            uint32_t off = (uint32_t)(c >> 4) * ACH + (uint32_t)r * 32
                         + ((uint32_t)((c & 15) * 2) ^ sw);
            *(uint2*)(sm + off)           = make_uint2(h01, h23);
            *(uint2*)(sm + off + 4 * ACH) = make_uint2(l01, l23);
        }
    }
    {
        int r = t >> 2, sub = t & 3;
        uint32_t sw = SWZ(r);
        const float4* wrow = (const float4*)(w + r * 64 + sub * 16);
#pragma unroll
        for (int g = 0; g < 4; g++) {
            float4 v = wrow[g];
            int c = sub * 16 + g * 4;
            uint32_t h01 = pack_f16(v.x, v.y);
            uint32_t h23 = pack_f16(v.z, v.w);
            uint32_t off = (uint32_t)(c >> 4) * BCH + (uint32_t)r * 32
                         + ((uint32_t)((c & 15) * 2) ^ sw);
            *(uint2*)(Bsm + off) = make_uint2(h01, h23);
        }
    }
    __syncthreads();

    int m0 = (wid & 3) * 32;
    int n0 = (wid >> 2) * 32;

    float acc[2][NT8][4];
#pragma unroll
    for (int mi = 0; mi < 2; mi++)
#pragma unroll
        for (int nj = 0; nj < NT8; nj++)
#pragma unroll
            for (int e = 0; e < 4; e++) acc[mi][nj][e] = 0.f;

    uint32_t a_addr[2], b_addr[NB4];
#pragma unroll
    for (int mi = 0; mi < 2; mi++) {
        uint32_t row = (uint32_t)(m0 + mi*16 + (lane & 15));
        a_addr[mi] = abase + row * 32 + (((uint32_t)(lane >> 4) << 4) ^ SWZ(row));
    }
#pragma unroll
    for (int nj = 0; nj < NB4; nj++) {
        uint32_t row = (uint32_t)(n0 + nj*16 + (lane & 7) + ((lane >> 4) << 3));
        b_addr[nj] = bbase + row * 32 + ((((uint32_t)(lane >> 3) & 1u) << 4) ^ SWZ(row));
    }

#pragma unroll
    for (int kc = 0; kc < NKC; kc++) {
        int bkc = kc & (NKB - 1);
        uint32_t af[2][4];
        ldm4(a_addr[0] + kc * ACH, af[0]);
        ldm4(a_addr[1] + kc * ACH, af[1]);
        uint32_t bf[NT8][2];
#pragma unroll
        for (int nj = 0; nj < NB4; nj++) {
            uint32_t tmp[4];
            ldm4(b_addr[nj] + bkc * BCH, tmp);
            bf[2*nj][0] = tmp[0]; bf[2*nj][1] = tmp[1];
            bf[2*nj+1][0] = tmp[2]; bf[2*nj+1][1] = tmp[3];
        }
#pragma unroll
        for (int mi = 0; mi < 2; mi++)
#pragma unroll
            for (int nj = 0; nj < NT8; nj++)
                mma_f16(acc[mi][nj], af[mi], bf[nj]);
    }

    int rq = lane >> 2, cq = (lane & 3) * 2;
    float ps[2*NT8], pq[2*NT8];
#pragma unroll
    for (int nj = 0; nj < NT8; nj++) {
        int col = n0 + nj*8 + cq;
        float b0 = sh_bias[col], b1 = sh_bias[col+1];
        float y00 = acc[0][nj][0] + b0, y01 = acc[0][nj][1] + b1;
        float y10 = acc[0][nj][2] + b0, y11 = acc[0][nj][3] + b1;
        float y20 = acc[1][nj][0] + b0, y21 = acc[1][nj][1] + b1;
        float y30 = acc[1][nj][2] + b0, y31 = acc[1][nj][3] + b1;
        size_t r0 = pos0 + m0 + rq;
        *(float2*)(g_y2 + r0 * 64 + col)        = make_float2(y00, y01);
        *(float2*)(g_y2 + (r0 + 8) * 64 + col)  = make_float2(y10, y11);
        *(float2*)(g_y2 + (r0 + 16) * 64 + col) = make_float2(y20, y21);
        *(float2*)(g_y2 + (r0 + 24) * 64 + col) = make_float2(y30, y31);
        ps[2*nj]   = y00 + y10 + y20 + y30;
        ps[2*nj+1] = y01 + y11 + y21 + y31;
        pq[2*nj]   = y00*y00 + y10*y10 + y20*y20 + y30*y30;
        pq[2*nj+1] = y01*y01 + y11*y11 + y21*y21 + y31*y31;
    }
    RQ_REDUCE(ps, 2*NT8);
    RQ_REDUCE(pq, 2*NT8);
    __syncthreads();
    float* wsum = (float*)sm;
    float* wsq  = wsum + 8 * NCH;
    if (lane < 4) {
#pragma unroll
        for (int nj = 0; nj < NT8; nj++) {
            int col = n0 + nj*8 + cq;
            wsum[wid*NCH + col]   = ps[2*nj];
            wsum[wid*NCH + col+1] = ps[2*nj+1];
            wsq[wid*NCH + col]    = pq[2*nj];
            wsq[wid*NCH + col+1]  = pq[2*nj+1];
        }
    }
    __syncthreads();
    if (t < NCH) {
        int wb = (t >= 32) ? 4 : 0;
        float s = 0.f, q = 0.f;
#pragma unroll
        for (int w2 = 0; w2 < 4; w2++) {
            s += wsum[(wb+w2)*NCH + t];
            q += wsq[(wb+w2)*NCH + t];
        }
        atomicAdd(&g_sum[1][t], (double)s);
        atomicAdd(&g_sq[1][t],  (double)q);
    }
}

// ---------------- layer 3: HMMA fp16 GEMM + shfl stats + per-query max/min ---
__global__ __launch_bounds__(256) void mm3_kernel(const float* __restrict__ w,
                                                  const float* __restrict__ bias)
{
    constexpr int NCH = 128;
    constexpr int ACH = 128 * 32;
    constexpr int NKC = 8;
    constexpr int NKB = 4;
    constexpr int ABYTES = NKC * ACH;       // 32768
    constexpr int BCH = NCH * 32;
    constexpr int BBYTES = NKB * BCH;       // 16384
    constexpr int NT8 = 8, NB4 = 4;

    extern __shared__ char dsm[];
    uint32_t raw = smem_u32(dsm);
    uint32_t abase = (raw + 1023) & ~1023u;
    char* sm  = dsm + (abase - raw);
    char* Bsm = sm + ABYTES;
    uint32_t bbase = abase + ABYTES;
    float* sh_bias = (float*)(Bsm + BBYTES);
    float* sh_sc = sh_bias + NCH;
    float* sh_sf = sh_sc + 64;

    int t = threadIdx.x;
    int wid = t >> 5, lane = t & 31;
    size_t pos0 = (size_t)blockIdx.x * 128;

    if (t < NCH) sh_bias[t] = bias[t];
    if (t < 64) { sh_sc[t] = g_scale[1][t]; sh_sf[t] = g_shift[1][t]; }
    __syncthreads();

    {
        int r = t >> 1, h = t & 1;
        uint32_t sw = SWZ(r);
        const float4* xrow = (const float4*)(g_y2 + (pos0 + r) * 64) + h * 8;
#pragma unroll
        for (int g = 0; g < 8; g++) {
            float4 v = xrow[g];
            int c = h * 32 + g * 4;
            float a0 = fmaxf(fmaf(v.x, sh_sc[c+0], sh_sf[c+0]), 0.f);
            float a1 = fmaxf(fmaf(v.y, sh_sc[c+1], sh_sf[c+1]), 0.f);
            float a2 = fmaxf(fmaf(v.z, sh_sc[c+2], sh_sf[c+2]), 0.f);
            float a3 = fmaxf(fmaf(v.w, sh_sc[c+3], sh_sf[c+3]), 0.f);
            uint32_t h01, l01, h23, l23;
            split_f16(a0, a1, h01, l01);
            split_f16(a2, a3, h23, l23);
            uint32_t off = (uint32_t)(c >> 4) * ACH + (uint32_t)r * 32
                         + ((uint32_t)((c & 15) * 2) ^ sw);
            *(uint2*)(sm + off)           = make_uint2(h01, h23);
            *(uint2*)(sm + off + 4 * ACH) = make_uint2(l01, l23);
        }
    }
    {
        int r = t >> 1, sub = t & 1;
        uint32_t sw = SWZ(r);
        const float4* wrow = (const float4*)(w + r * 64 + sub * 32);
#pragma unroll
        for (int g = 0; g < 8; g++) {
            float4 v = wrow[g];
            int c = sub * 32 + g * 4;
            uint32_t h01 = pack_f16(v.x, v.y);
            uint32_t h23 = pack_f16(v.z, v.w);
            uint32_t off = (uint32_t)(c >> 4) * BCH + (uint32_t)r * 32
                         + ((uint32_t)((c & 15) * 2) ^ sw);
            *(uint2*)(Bsm + off) = make_uint2(h01, h23);
        }
    }
    __syncthreads();

    int m0 = (wid & 3) * 32;
    int n0 = (wid >> 2) * 64;

    float acc[2][NT8][4];
#pragma unroll
    for (int mi = 0; mi < 2; mi++)
#pragma unroll
        for (int nj = 0; nj < NT8; nj++)
#pragma unroll
            for (int e = 0; e < 4; e++) acc[mi][nj][e] = 0.f;

    uint32_t a_addr[2], b_addr[NB4];
#pragma unroll
    for (int mi = 0; mi < 2; mi++) {
        uint32_t row = (uint32_t)(m0 + mi*16 + (lane & 15));
        a_addr[mi] = abase + row * 32 + (((uint32_t)(lane >> 4) << 4) ^ SWZ(row));
    }
#pragma unroll
    for (int nj = 0; nj < NB4; nj++) {
        uint32_t row = (uint32_t)(n0 + nj*16 + (lane & 7) + ((lane >> 4) << 3));
        b_addr[nj] = bbase + row * 32 + ((((uint32_t)(lane >> 3) & 1u) << 4) ^ SWZ(row));
    }

#pragma unroll
    for (int kc = 0; kc < NKC; kc++) {
        int bkc = kc & (NKB - 1);
        uint32_t af[2][4];
        ldm4(a_addr[0] + kc * ACH, af[0]);
        ldm4(a_addr[1] + kc * ACH, af[1]);
        uint32_t bf[NT8][2];
#pragma unroll
        for (int nj = 0; nj < NB4; nj++) {
            uint32_t tmp[4];
            ldm4(b_addr[nj] + bkc * BCH, tmp);
            bf[2*nj][0] = tmp[0]; bf[2*nj][1] = tmp[1];
            bf[2*nj+1][0] = tmp[2]; bf[2*nj+1][1] = tmp[3];
        }
#pragma unroll
        for (int mi = 0; mi < 2; mi++)
#pragma unroll
            for (int nj = 0; nj < NT8; nj++)
                mma_f16(acc[mi][nj], af[mi], bf[nj]);
    }

    // ---- epilogue: bias, shfl stats, per-query max/min (no global y3) ----
    int rq = lane >> 2, cq = (lane & 3) * 2;
    int q = wid & 3;
    float ps[2*NT8], pq[2*NT8];
    float tmax[NT8][2], tmin[NT8][2];
#pragma unroll
    for (int nj = 0; nj < NT8; nj++) {
        int col = n0 + nj*8 + cq;
        float b0 = sh_bias[col], b1 = sh_bias[col+1];
        float y00 = acc[0][nj][0] + b0, y01 = acc[0][nj][1] + b1;
        float y10 = acc[0][nj][2] + b0, y11 = acc[0][nj][3] + b1;
        float y20 = acc[1][nj][0] + b0, y21 = acc[1][nj][1] + b1;
        float y30 = acc[1][nj][2] + b0, y31 = acc[1][nj][3] + b1;
        tmax[nj][0] = fmaxf(fmaxf(y00, y10), fmaxf(y20, y30));
        tmax[nj][1] = fmaxf(fmaxf(y01, y11), fmaxf(y21, y31));
        tmin[nj][0] = fminf(fminf(y00, y10), fminf(y20, y30));
        tmin[nj][1] = fminf(fminf(y01, y11), fminf(y21, y31));
        ps[2*nj]   = y00 + y10 + y20 + y30;
        ps[2*nj+1] = y01 + y11 + y21 + y31;
        pq[2*nj]   = y00*y00 + y10*y10 + y20*y20 + y30*y30;
        pq[2*nj+1] = y01*y01 + y11*y11 + y21*y21 + y31*y31;
    }
    RQ_REDUCE(ps, 2*NT8);
    RQ_REDUCE(pq, 2*NT8);
    __syncthreads();              // all A/B smem reads complete; reuse regions

    float* shmx = (float*)sm;                    // 16 KB (A region): [q*8+rq][128]
    float* shmn = (float*)(sm + 16384);          // 16 KB (A region)
    float* wsum = (float*)(sm + 32768);          // 4 KB: [8][128]
    float* wsq  = (float*)(sm + 36864);          // 4 KB
#pragma unroll
    for (int nj = 0; nj < NT8; nj++) {
        int col = n0 + nj*8 + cq;
        int idx = (q * 8 + rq) * 128 + col;
        *(float2*)&shmx[idx] = make_float2(tmax[nj][0], tmax[nj][1]);
        *(float2*)&shmn[idx] = make_float2(tmin[nj][0], tmin[nj][1]);
    }
    if (lane < 4) {
#pragma unroll
        for (int nj = 0; nj < NT8; nj++) {
            int col = n0 + nj*8 + cq;
            wsum[wid*NCH + col]   = ps[2*nj];
            wsum[wid*NCH + col+1] = ps[2*nj+1];
            wsq[wid*NCH + col]    = pq[2*nj];
            wsq[wid*NCH + col+1]  = pq[2*nj+1];
        }
    }
    __syncthreads();

    if (t < 128) {
        int wb = (t >= 64) ? 4 : 0;
        float s = 0.f, qq = 0.f;
#pragma unroll
        for (int w2 = 0; w2 < 4; w2++) {
            s += wsum[(wb+w2)*NCH + t];
            qq += wsq[(wb+w2)*NCH + t];
        }
        atomicAdd(&g_sum[2][t], (double)s);
        atomicAdd(&g_sq[2][t],  (double)qq);
    }
#pragma unroll
    for (int u = t; u < 512; u += 256) {
        int uq = u >> 7, col = u & 127;
        float m = shmx[(uq * 8) * 128 + col];
        float n = shmn[(uq * 8) * 128 + col];
#pragma unroll
        for (int p = 1; p < 8; p++) {
            m = fmaxf(m, shmx[(uq * 8 + p) * 128 + col]);
            n = fminf(n, shmn[(uq * 8 + p) * 128 + col]);
        }
        size_t gq = (size_t)blockIdx.x * 4 + uq;
        g_mx[(size_t)col * QTOT + gq] = m;
        g_mn[(size_t)col * QTOT + gq] = n;
    }
}

// ---------------- final: affine+relu on (max,min), coalesced -----------------
__global__ void final_kernel(float* __restrict__ out) {
    int ch = blockIdx.x >> 6;
    int q  = ((blockIdx.x & 63) << 8) + threadIdx.x;
    float sc = g_scale[2][ch], sh = g_shift[2][ch];
    float mx = g_mx[(size_t)ch * QTOT + q];
    float mn = g_mn[(size_t)ch * QTOT + q];
    float v = fmaxf(fmaxf(fmaf(sc, mx, sh), fmaf(sc, mn, sh)), 0.f);
    int b = q >> 10, s = q & 1023;
    out[OUT_OFF + ((size_t)b * 128 + ch) * SS + s] = v;
}

// ---------------- launcher ----------------------------------------------------
extern "C" void kernel_launch(void* const* d_in, const int* in_sizes, int n_in,
                              void* d_out, int out_size) {
    (void)in_sizes; (void)n_in; (void)out_size;
    const float* xyz    = (const float*)d_in[0];
    const float* points = (const float*)d_in[1];
    const float* w1  = (const float*)d_in[2];
    const float* b1  = (const float*)d_in[3];
    const float* g1  = (const float*)d_in[4];
    const float* be1 = (const float*)d_in[5];
    const float* w2  = (const float*)d_in[6];
    const float* b2  = (const float*)d_in[7];
    const float* g2  = (const float*)d_in[8];
    const float* be2 = (const float*)d_in[9];
    const float* w3  = (const float*)d_in[10];
    const float* b3  = (const float*)d_in[11];
    const float* g3  = (const float*)d_in[12];
    const float* be3 = (const float*)d_in[13];
    float* out = (float*)d_out;

    const int DYN1 = 1024 + 40960 + 10240 + 1024;   // 53248
    const int DYN2 = 1024 + 32768 + 8192 + 2048;    // 44032
    const int DYN3 = 1024 + 32768 + 16384 + 2048;   // 52224
    cudaFuncSetAttribute(mm1_kernel, cudaFuncAttributeMaxDynamicSharedMemorySize, DYN1);
    cudaFuncSetAttribute(mm2_kernel, cudaFuncAttributeMaxDynamicSharedMemorySize, DYN2);
    cudaFuncSetAttribute(mm3_kernel, cudaFuncAttributeMaxDynamicSharedMemorySize, DYN3);

    init_kernel<<<1, 512>>>();
    fps_kernel<<<BB, 1024>>>(xyz);
    gather_newxyz_kernel<<<(QTOT + 255) / 256, 256>>>(xyz, out);
    qb_kernel<<<(QTOT) / 8, 256>>>(xyz);

    mm1_kernel<<<MTOT / 128, 256, DYN1>>>(xyz, points, out, w1, b1);
    stats_kernel<<<1, 128>>>(0, g1, be1, 64);

    mm2_kernel<<<MTOT / 128, 256, DYN2>>>(w2, b2);
    stats_kernel<<<1, 128>>>(1, g2, be2, 64);

    mm3_kernel<<<MTOT / 128, 256, DYN3>>>(w3, b3);
    stats_kernel<<<1, 128>>>(2, g3, be3, 128);

    final_kernel<<<128 * 64, 256>>>(out);
}

// round 17
// speedup vs baseline: 1.5857x; 1.0041x over previous
#include <cuda_runtime.h>
#include <cuda_bf16.h>
#include <cstdint>
#include <cstddef>

#define BB 16
#define NN 8192
#define SS 1024
#define KK 32
#define R2C 0.04f          /* float(0.2**2) */
#define EPSC 1e-5f
#define MTOT (BB*SS*KK)    /* 524288 positions */
#define QTOT (BB*SS)       /* 16384 queries */
#define OUT_OFF (BB*SS*3)

typedef unsigned long long ull;

// ---------------- packed f32x2 helpers ----------------------------------------
__device__ __forceinline__ ull fma2(ull a, ull b, ull c) {
    ull d; asm("fma.rn.f32x2 %0,%1,%2,%3;" : "=l"(d) : "l"(a), "l"(b), "l"(c)); return d;
}
__device__ __forceinline__ ull mul2(ull a, ull b) {
    ull d; asm("mul.rn.f32x2 %0,%1,%2;" : "=l"(d) : "l"(a), "l"(b)); return d;
}
__device__ __forceinline__ ull add2(ull a, ull b) {
    ull d; asm("add.rn.f32x2 %0,%1,%2;" : "=l"(d) : "l"(a), "l"(b)); return d;
}
__device__ __forceinline__ ull dup2(float x) {
    ull d; asm("mov.b64 %0,{%1,%1};" : "=l"(d) : "f"(x)); return d;
}
__device__ __forceinline__ ull pk2(float lo, float hi) {
    ull d; asm("mov.b64 %0,{%1,%2};" : "=l"(d) : "f"(lo), "f"(hi)); return d;
}
__device__ __forceinline__ float2 up2(ull v) {
    float2 r; asm("mov.b64 {%0,%1},%2;" : "=f"(r.x), "=f"(r.y) : "l"(v)); return r;
}

// ---------------- HMMA / ldmatrix helpers (baseline PTX, sm_103-safe) ---------
__device__ __forceinline__ uint32_t smem_u32(const void* p) {
    uint32_t a;
    asm("{ .reg .u64 t; cvta.to.shared.u64 t, %1; cvt.u32.u64 %0, t; }" : "=r"(a) : "l"(p));
    return a;
}
__device__ __forceinline__ void ldm4(uint32_t addr, uint32_t* r) {
    asm volatile("ldmatrix.sync.aligned.m8n8.x4.shared.b16 {%0,%1,%2,%3}, [%4];"
                 : "=r"(r[0]), "=r"(r[1]), "=r"(r[2]), "=r"(r[3]) : "r"(addr));
}
__device__ __forceinline__ void mma_f16(float* c, const uint32_t* a, const uint32_t* b) {
    asm volatile(
        "mma.sync.aligned.m16n8k16.row.col.f32.f16.f16.f32 "
        "{%0,%1,%2,%3}, {%4,%5,%6,%7}, {%8,%9}, {%0,%1,%2,%3};"
        : "+f"(c[0]), "+f"(c[1]), "+f"(c[2]), "+f"(c[3])
        : "r"(a[0]), "r"(a[1]), "r"(a[2]), "r"(a[3]), "r"(b[0]), "r"(b[1]));
}

// split fp32 pair -> packed fp16 highs + packed fp16 residuals (a ~= ah + al)
__device__ __forceinline__ void split_f16(float a, float b, uint32_t& hi, uint32_t& lo) {
    asm("{.reg .b16 ha,hb,la,lb;\n"
        " .reg .f32 fa,fb;\n"
        " cvt.rn.f16.f32 ha, %2;\n"
        " cvt.rn.f16.f32 hb, %3;\n"
        " cvt.f32.f16 fa, ha;\n"
        " cvt.f32.f16 fb, hb;\n"
        " sub.f32 fa, %2, fa;\n"
        " sub.f32 fb, %3, fb;\n"
        " cvt.rn.f16.f32 la, fa;\n"
        " cvt.rn.f16.f32 lb, fb;\n"
        " mov.b32 %0, {ha,hb};\n"
        " mov.b32 %1, {la,lb};}"
        : "=r"(hi), "=r"(lo) : "f"(a), "f"(b));
}
__device__ __forceinline__ uint32_t pack_f16(float a, float b) {
    uint32_t r;
    asm("{.reg .b16 x,y; cvt.rn.f16.f32 x,%1; cvt.rn.f16.f32 y,%2; mov.b32 %0,{x,y};}"
        : "=r"(r) : "f"(a), "f"(b));
    return r;
}

// ---------------- device scratch ----------------------------------------------
__device__ int    g_fps[QTOT];
__device__ int    g_idx[(size_t)QTOT*KK];
__device__ float  g_y1[(size_t)MTOT*64];
__device__ float  g_y2[(size_t)MTOT*64];
__device__ float  g_mx[(size_t)128*QTOT];   // [ch][q]
__device__ float  g_mn[(size_t)128*QTOT];
__device__ double g_sum[3][128];
__device__ double g_sq[3][128];
__device__ float  g_scale[3][128];
__device__ float  g_shift[3][128];

// ---------------- init --------------------------------------------------------
__global__ void init_kernel() {
    int t = blockIdx.x * blockDim.x + threadIdx.x;
    if (t < 3 * 128) {
        ((double*)g_sum)[t] = 0.0;
        ((double*)g_sq)[t]  = 0.0;
    }
}

// ---------------- farthest point sampling: packed dist math, smem xyz ---------
__global__ __launch_bounds__(1024) void fps_kernel(const float* __restrict__ xyz) {
    int b = blockIdx.x;
    int t = threadIdx.x;
    int lane = t & 31, w = t >> 5;
    const float* xb = xyz + (size_t)b * NN * 3;

    extern __shared__ float s_xyz[];       // NN*3 floats = 96 KB
    __shared__ ull s_key[2][32];

    ull px2[4], py2[4], pz2[4];
    float dist[8];
#pragma unroll
    for (int j = 0; j < 4; j++) {
        int p0 = t + (2*j)   * 1024;
        int p1 = t + (2*j+1) * 1024;
        px2[j] = pk2(xb[p0*3+0], xb[p1*3+0]);
        py2[j] = pk2(xb[p0*3+1], xb[p1*3+1]);
        pz2[j] = pk2(xb[p0*3+2], xb[p1*3+2]);
    }
#pragma unroll
    for (int i = 0; i < 8; i++) dist[i] = 1e10f;
    for (int i = t; i < NN * 3; i += 1024) s_xyz[i] = xb[i];

    int far = 0;
    int buf = 0;
    __syncthreads();

    for (int it = 0; it < SS; it++) {
        if (t == 0) g_fps[b * SS + it] = far;
        float cx = s_xyz[far*3+0], cy = s_xyz[far*3+1], cz = s_xyz[far*3+2];
        ull ncx = dup2(-cx), ncy = dup2(-cy), ncz = dup2(-cz);

#pragma unroll
        for (int j = 0; j < 4; j++) {
            ull dx = add2(px2[j], ncx);
            ull dy = add2(py2[j], ncy);
            ull dz = add2(pz2[j], ncz);
            ull d2 = mul2(dx, dx);
            d2 = fma2(dy, dy, d2);
            d2 = fma2(dz, dz, d2);
            float2 dd = up2(d2);
            dist[2*j]   = fminf(dist[2*j],   dd.x);
            dist[2*j+1] = fminf(dist[2*j+1], dd.y);
        }
        // out-of-loop argmax: max tree, then descending first-match = min index
        float m01 = fmaxf(dist[0], dist[1]);
        float m23 = fmaxf(dist[2], dist[3]);
        float m45 = fmaxf(dist[4], dist[5]);
        float m67 = fmaxf(dist[6], dist[7]);
        float bestv = fmaxf(fmaxf(m01, m23), fmaxf(m45, m67));

        int besti = 0;
#pragma unroll
        for (int i = 7; i >= 0; i--)
            if (dist[i] == bestv) besti = t + i * 1024;

        unsigned bits = __float_as_uint(bestv);
        unsigned mh = __reduce_max_sync(0xffffffffu, bits);
        unsigned ml = __reduce_max_sync(0xffffffffu, (bits == mh) ? ~(unsigned)besti : 0u);
        if (lane == 0) s_key[buf][w] = ((ull)mh << 32) | ml;
        __syncthreads();
        ull k = s_key[buf][lane];
        unsigned h2 = (unsigned)(k >> 32);
        unsigned m2 = __reduce_max_sync(0xffffffffu, h2);
        unsigned l2 = __reduce_max_sync(0xffffffffu, (h2 == m2) ? (unsigned)k : 0u);
        far = (int)(~l2);
        buf ^= 1;
    }
}

// ---------------- gather new_xyz into output ---------------------------------
__global__ void gather_newxyz_kernel(const float* __restrict__ xyz,
                                     float* __restrict__ out) {
    int i = blockIdx.x * blockDim.x + threadIdx.x;
    if (i < QTOT) {
        int b = i >> 10;
        int j = g_fps[i];
        const float* p = xyz + ((size_t)b * NN + j) * 3;
        out[i*3+0] = p[0];
        out[i*3+1] = p[1];
        out[i*3+2] = p[2];
    }
}

// ---------------- ball query: one warp per query, 1-deep prefetch ------------
__global__ void qb_kernel(const float* __restrict__ xyz) {
    int q = (blockIdx.x * blockDim.x + threadIdx.x) >> 5;
    int lane = threadIdx.x & 31;
    int b = q >> 10;
    const float* xb = xyz + (size_t)b * NN * 3;
    int c = g_fps[q];
    float cx = xb[c*3+0], cy = xb[c*3+1], cz = xb[c*3+2];

    int cnt = 0;
    int first = 0;
    bool have_first = false;
    int* out = g_idx + (size_t)q * KK;

    int p = lane;
    float x = xb[p*3+0], y = xb[p*3+1], z = xb[p*3+2];

    for (int base = 0; base < NN; base += 32) {
        float nx = 0.f, ny = 0.f, nz = 0.f;
        if (base + 32 < NN) {
            int pn = base + 32 + lane;
            nx = xb[pn*3+0]; ny = xb[pn*3+1]; nz = xb[pn*3+2];
        }
        float dx = x - cx, dy = y - cy, dz = z - cz;
        float d = dx*dx + dy*dy + dz*dz;
        bool in = (d <= R2C);
        unsigned m = __ballot_sync(0xffffffffu, in);
        if (m) {
            int pos = cnt + __popc(m & ((1u << lane) - 1u));
            if (in && pos < KK) out[pos] = p;
            if (!have_first) { first = base + __ffs(m) - 1; have_first = true; }
            cnt += __popc(m);
            if (cnt >= KK) break;
        }
        p = base + 32 + lane; x = nx; y = ny; z = nz;
    }
    for (int pos = cnt + lane; pos < KK; pos += 32) out[pos] = first;
}

// ---------------- per-channel BN fold ----------------------------------------
__global__ void stats_kernel(int L, const float* __restrict__ gam,
                             const float* __restrict__ bet, int C) {
    int t = threadIdx.x;
    if (t < C) {
        double mean = g_sum[L][t] * (1.0 / (double)MTOT);
        double var  = g_sq[L][t]  * (1.0 / (double)MTOT) - mean * mean;
        float sc = gam[t] * rsqrtf((float)var + EPSC);
        g_scale[L][t] = sc;
        g_shift[L][t] = fmaf(-(float)mean, sc, bet[t]);
    }
}

// shfl butterfly over the 8 rq-lanes (xor 4, 8, 16)
#define RQ_REDUCE(arr, cnt)                                             \
    _Pragma("unroll")                                                   \
    for (int _mask = 4; _mask <= 16; _mask <<= 1)                       \
        _Pragma("unroll")                                               \
        for (int _i = 0; _i < (cnt); _i++)                              \
            (arr)[_i] += __shfl_xor_sync(0xffffffffu, (arr)[_i], _mask);

// bank-conflict swizzle: flip the 16B half with row bit 2
#define SWZ(r) ((((uint32_t)(r) >> 2) & 1u) << 4)

// ---------------- layer 1: HMMA gather-GEMM (K=67 pad 80 -> 64) + stats ------
// fp16 2-term split: A' = [ah(80) | al(80)]; B single copy, indexed kc%5.
// k-channel order: 0..63 = points, 64..66 = xyz-norm, 67..79 = zero pad.
__global__ __launch_bounds__(256) void mm1_kernel(
    const float* __restrict__ xyz, const float* __restrict__ points,
    const float* __restrict__ newxyz,
    const float* __restrict__ w, const float* __restrict__ bias)
{
    constexpr int NCH = 64;
    constexpr int ACH = 128 * 32;           // 4096 B per A k-chunk
    constexpr int NKC = 10;                 // A chunks (5 ah + 5 al)
    constexpr int NKB = 5;                  // B chunks (single copy)
    constexpr int ABYTES = NKC * ACH;       // 40960
    constexpr int BCH = NCH * 32;           // 2048
    constexpr int BBYTES = NKB * BCH;       // 10240
    constexpr int NT8 = 4, NB4 = 2;

    extern __shared__ char dsm[];
    uint32_t raw = smem_u32(dsm);
    uint32_t abase = (raw + 1023) & ~1023u;
    char* sm  = dsm + (abase - raw);
    char* Bsm = sm + ABYTES;
    uint32_t bbase = abase + ABYTES;
    float* sh_bias = (float*)(Bsm + BBYTES);

    int t = threadIdx.x;
    int wid = t >> 5, lane = t & 31;
    size_t pos0 = (size_t)blockIdx.x * 128;

    if (t < NCH) sh_bias[t] = bias[t];

    // ---- stage A: 2 threads per row ----
    {
        int r = t >> 1, h = t & 1;
        size_t pos = pos0 + r;
        int j = g_idx[pos];
        int b = (int)(pos >> 15);
        int s = (int)((pos >> 5) & 1023);
        uint32_t sw = SWZ(r);
        const float4* prow = (const float4*)(points + ((size_t)b * NN + j) * 64) + h * 8;
#pragma unroll
        for (int g = 0; g < 8; g++) {
            float4 v = prow[g];
            int c = h * 32 + g * 4;
            uint32_t h01, l01, h23, l23;
            split_f16(v.x, v.y, h01, l01);
            split_f16(v.z, v.w, h23, l23);
            uint32_t off = (uint32_t)(c >> 4) * ACH + (uint32_t)r * 32
                         + ((uint32_t)((c & 15) * 2) ^ sw);
            *(uint2*)(sm + off)           = make_uint2(h01, h23);   // ah
            *(uint2*)(sm + off + 5 * ACH) = make_uint2(l01, l23);   // al
        }
        if (!h) {
            const float* xr = xyz + ((size_t)b * NN + j) * 3;
            const float* nr = newxyz + ((size_t)b * SS + s) * 3;
            float x0 = xr[0] - nr[0], x1 = xr[1] - nr[1], x2 = xr[2] - nr[2];
            uint32_t h01, l01, h23, l23;
            split_f16(x0, x1, h01, l01);
            split_f16(x2, 0.f, h23, l23);
            uint32_t base = 4 * ACH + (uint32_t)r * 32;
            uint2 z = make_uint2(0u, 0u);
            *(uint2*)(sm + base + (0u ^ sw))            = make_uint2(h01, h23);
            *(uint2*)(sm + base + (8u ^ sw))            = z;
            *(uint2*)(sm + base + (16u ^ sw))           = z;
            *(uint2*)(sm + base + (24u ^ sw))           = z;
            *(uint2*)(sm + base + 5*ACH + (0u ^ sw))    = make_uint2(l01, l23);
            *(uint2*)(sm + base + 5*ACH + (8u ^ sw))    = z;
            *(uint2*)(sm + base + 5*ACH + (16u ^ sw))   = z;
            *(uint2*)(sm + base + 5*ACH + (24u ^ sw))   = z;
        }
    }
    // ---- stage B: w1 rows, permuted channels, single fp16 copy ----
    {
        int r = t >> 2, sub = t & 3;
        uint32_t sw = SWZ(r);
        const float* wr = w + r * 67;
#pragma unroll
        for (int g = 0; g < 5; g++) {
            int kq = sub * 20 + g * 4;
            float v[4];
#pragma unroll
            for (int i = 0; i < 4; i++) {
                int kc = kq + i;
                v[i] = (kc < 64) ? wr[3 + kc] : ((kc < 67) ? wr[kc - 64] : 0.f);
            }
            uint32_t h01 = pack_f16(v[0], v[1]);
            uint32_t h23 = pack_f16(v[2], v[3]);
            uint32_t off = (uint32_t)(kq >> 4) * BCH + (uint32_t)r * 32
                         + ((uint32_t)((kq & 15) * 2) ^ sw);
            *(uint2*)(Bsm + off) = make_uint2(h01, h23);
        }
    }
    __syncthreads();

    int m0 = (wid & 3) * 32;
    int n0 = (wid >> 2) * 32;

    float acc[2][NT8][4];
#pragma unroll
    for (int mi = 0; mi < 2; mi++)
#pragma unroll
        for (int nj = 0; nj < NT8; nj++)
#pragma unroll
            for (int e = 0; e < 4; e++) acc[mi][nj][e] = 0.f;

    uint32_t a_addr[2], b_addr[NB4];
#pragma unroll
    for (int mi = 0; mi < 2; mi++) {
        uint32_t row = (uint32_t)(m0 + mi*16 + (lane & 15));
        a_addr[mi] = abase + row * 32 + (((uint32_t)(lane >> 4) << 4) ^ SWZ(row));
    }
#pragma unroll
    for (int nj = 0; nj < NB4; nj++) {
        uint32_t row = (uint32_t)(n0 + nj*16 + (lane & 7) + ((lane >> 4) << 3));
        b_addr[nj] = bbase + row * 32 + ((((uint32_t)(lane >> 3) & 1u) << 4) ^ SWZ(row));
    }

#pragma unroll
    for (int kc = 0; kc < NKC; kc++) {
        int bkc = (kc < NKB) ? kc : kc - NKB;
        uint32_t af[2][4];
        ldm4(a_addr[0] + kc * ACH, af[0]);
        ldm4(a_addr[1] + kc * ACH, af[1]);
        uint32_t bf[NT8][2];
#pragma unroll
        for (int nj = 0; nj < NB4; nj++) {
            uint32_t tmp[4];
            ldm4(b_addr[nj] + bkc * BCH, tmp);
            bf[2*nj][0] = tmp[0]; bf[2*nj][1] = tmp[1];
            bf[2*nj+1][0] = tmp[2]; bf[2*nj+1][1] = tmp[3];
        }
#pragma unroll
        for (int mi = 0; mi < 2; mi++)
#pragma unroll
            for (int nj = 0; nj < NT8; nj++)
                mma_f16(acc[mi][nj], af[mi], bf[nj]);
    }

    // ---- epilogue: bias + store + shfl-reduced stats ----
    int rq = lane >> 2, cq = (lane & 3) * 2;
    float ps[2*NT8], pq[2*NT8];
#pragma unroll
    for (int nj = 0; nj < NT8; nj++) {
        int col = n0 + nj*8 + cq;
        float b0 = sh_bias[col], b1 = sh_bias[col+1];
        float y00 = acc[0][nj][0] + b0, y01 = acc[0][nj][1] + b1;
        float y10 = acc[0][nj][2] + b0, y11 = acc[0][nj][3] + b1;
        float y20 = acc[1][nj][0] + b0, y21 = acc[1][nj][1] + b1;
        float y30 = acc[1][nj][2] + b0, y31 = acc[1][nj][3] + b1;
        size_t r0 = pos0 + m0 + rq;
        *(float2*)(g_y1 + r0 * 64 + col)        = make_float2(y00, y01);
        *(float2*)(g_y1 + (r0 + 8) * 64 + col)  = make_float2(y10, y11);
        *(float2*)(g_y1 + (r0 + 16) * 64 + col) = make_float2(y20, y21);
        *(float2*)(g_y1 + (r0 + 24) * 64 + col) = make_float2(y30, y31);
        ps[2*nj]   = y00 + y10 + y20 + y30;
        ps[2*nj+1] = y01 + y11 + y21 + y31;
        pq[2*nj]   = y00*y00 + y10*y10 + y20*y20 + y30*y30;
        pq[2*nj+1] = y01*y01 + y11*y11 + y21*y21 + y31*y31;
    }
    RQ_REDUCE(ps, 2*NT8);
    RQ_REDUCE(pq, 2*NT8);
    __syncthreads();
    float* wsum = (float*)sm;              // [8][NCH]
    float* wsq  = wsum + 8 * NCH;
    if (lane < 4) {
#pragma unroll
        for (int nj = 0; nj < NT8; nj++) {
            int col = n0 + nj*8 + cq;
            wsum[wid*NCH + col]   = ps[2*nj];
            wsum[wid*NCH + col+1] = ps[2*nj+1];
            wsq[wid*NCH + col]    = pq[2*nj];
            wsq[wid*NCH + col+1]  = pq[2*nj+1];
        }
    }
    __syncthreads();
    if (t < NCH) {
        int wb = (t >= 32) ? 4 : 0;
        float s = 0.f, q = 0.f;
#pragma unroll
        for (int w2 = 0; w2 < 4; w2++) {
            s += wsum[(wb+w2)*NCH + t];
            q += wsq[(wb+w2)*NCH + t];
        }
        atomicAdd(&g_sum[0][t], (double)s);
        atomicAdd(&g_sq[0][t],  (double)q);
    }
}

// ---------------- layer 2: HMMA fp16 2-term GEMM + shfl stats ----------------
__global__ __launch_bounds__(256) void mm2_kernel(const float* __restrict__ w,
                                                  const float* __restrict__ bias)
{
    constexpr int NCH = 64;
    constexpr int ACH = 128 * 32;
    constexpr int NKC = 8;                  // A chunks (4 ah + 4 al)
    constexpr int NKB = 4;                  // B chunks (single copy)
    constexpr int ABYTES = NKC * ACH;       // 32768
    constexpr int BCH = NCH * 32;
    constexpr int BBYTES = NKB * BCH;       // 8192
    constexpr int NT8 = 4, NB4 = 2;

    extern __shared__ char dsm[];
    uint32_t raw = smem_u32(dsm);
    uint32_t abase = (raw + 1023) & ~1023u;
    char* sm  = dsm + (abase - raw);
    char* Bsm = sm + ABYTES;
    uint32_t bbase = abase + ABYTES;
    float* sh_bias = (float*)(Bsm + BBYTES);
    float* sh_sc = sh_bias + NCH;
    float* sh_sf = sh_sc + 64;

    int t = threadIdx.x;
    int wid = t >> 5, lane = t & 31;
    size_t pos0 = (size_t)blockIdx.x * 128;

    if (t < NCH) sh_bias[t] = bias[t];
    if (t < 64) { sh_sc[t] = g_scale[0][t]; sh_sf[t] = g_shift[0][t]; }
    __syncthreads();

    {
        int r = t >> 1, h = t & 1;
        uint32_t sw = SWZ(r);
        const float4* xrow = (const float4*)(g_y1 + (pos0 + r) * 64) + h * 8;
#pragma unroll
        for (int g = 0; g < 8; g++) {
            float4 v = xrow[g];
            int c = h * 32 + g * 4;
            float a0 = fmaxf(fmaf(v.x, sh_sc[c+0], sh_sf[c+0]), 0.f);
            float a1 = fmaxf(fmaf(v.y, sh_sc[c+1], sh_sf[c+1]), 0.f);
            float a2 = fmaxf(fmaf(v.z, sh_sc[c+2], sh_sf[c+2]), 0.f);
            float a3 = fmaxf(fmaf(v.w, sh_sc[c+3], sh_sf[c+3]), 0.f);
            uint32_t h01, l01, h23, l23;
            split_f16(a0, a1, h01, l01);
            split_f16(a2, a3, h23, l23);
            uint32_t off = (uint32_t)(c >> 4) * ACH + (uint32_t)r * 32
                         + ((uint32_t)((c & 15) * 2) ^ sw);
            *(uint2*)(sm + off)           = make_uint2(h01, h23);
            *(uint2*)(sm + off + 4 * ACH) = make_uint2(l01, l23);
        }
    }
    {
        int r = t >> 2, sub = t & 3;
        uint32_t sw = SWZ(r);
        const float4* wrow = (const float4*)(w + r * 64 + sub * 16);
#pragma unroll
        for (int g = 0; g < 4; g++) {
            float4 v = wrow[g];
            int c = sub * 16 + g * 4;
            uint32_t h01 = pack_f16(v.x, v.y);
            uint32_t h23 = pack_f16(v.z, v.w);
            uint32_t off = (uint32_t)(c >> 4) * BCH + (uint32_t)r * 32
                         + ((uint32_t)((c & 15) * 2) ^ sw);
            *(uint2*)(Bsm + off) = make_uint2(h01, h23);
        }
    }
    __syncthreads();

    int m0 = (wid & 3) * 32;
    int n0 = (wid >> 2) * 32;

    float acc[2][NT8][4];
#pragma unroll
    for (int mi = 0; mi < 2; mi++)
#pragma unroll
        for (int nj = 0; nj < NT8; nj++)
#pragma unroll
            for (int e = 0; e < 4; e++) acc[mi][nj][e] = 0.f;

    uint32_t a_addr[2], b_addr[NB4];
#pragma unroll
    for (int mi = 0; mi < 2; mi++) {
        uint32_t row = (uint32_t)(m0 + mi*16 + (lane & 15));
        a_addr[mi] = abase + row * 32 + (((uint32_t)(lane >> 4) << 4) ^ SWZ(row));
    }
#pragma unroll
    for (int nj = 0; nj < NB4; nj++) {
        uint32_t row = (uint32_t)(n0 + nj*16 + (lane & 7) + ((lane >> 4) << 3));
        b_addr[nj] = bbase + row * 32 + ((((uint32_t)(lane >> 3) & 1u) << 4) ^ SWZ(row));
    }

#pragma unroll
    for (int kc = 0; kc < NKC; kc++) {
        int bkc = kc & (NKB - 1);
        uint32_t af[2][4];
        ldm4(a_addr[0] + kc * ACH, af[0]);
        ldm4(a_addr[1] + kc * ACH, af[1]);
        uint32_t bf[NT8][2];
#pragma unroll
        for (int nj = 0; nj < NB4; nj++) {
            uint32_t tmp[4];
            ldm4(b_addr[nj] + bkc * BCH, tmp);
            bf[2*nj][0] = tmp[0]; bf[2*nj][1] = tmp[1];
            bf[2*nj+1][0] = tmp[2]; bf[2*nj+1][1] = tmp[3];
        }
#pragma unroll
        for (int mi = 0; mi < 2; mi++)
#pragma unroll
            for (int nj = 0; nj < NT8; nj++)
                mma_f16(acc[mi][nj], af[mi], bf[nj]);
    }

    int rq = lane >> 2, cq = (lane & 3) * 2;
    float ps[2*NT8], pq[2*NT8];
#pragma unroll
    for (int nj = 0; nj < NT8; nj++) {
        int col = n0 + nj*8 + cq;
        float b0 = sh_bias[col], b1 = sh_bias[col+1];
        float y00 = acc[0][nj][0] + b0, y01 = acc[0][nj][1] + b1;
        float y10 = acc[0][nj][2] + b0, y11 = acc[0][nj][3] + b1;
        float y20 = acc[1][nj][0] + b0, y21 = acc[1][nj][1] + b1;
        float y30 = acc[1][nj][2] + b0, y31 = acc[1][nj][3] + b1;
        size_t r0 = pos0 + m0 + rq;
        *(float2*)(g_y2 + r0 * 64 + col)        = make_float2(y00, y01);
        *(float2*)(g_y2 + (r0 + 8) * 64 + col)  = make_float2(y10, y11);
        *(float2*)(g_y2 + (r0 + 16) * 64 + col) = make_float2(y20, y21);
        *(float2*)(g_y2 + (r0 + 24) * 64 + col) = make_float2(y30, y31);
        ps[2*nj]   = y00 + y10 + y20 + y30;
        ps[2*nj+1] = y01 + y11 + y21 + y31;
        pq[2*nj]   = y00*y00 + y10*y10 + y20*y20 + y30*y30;
        pq[2*nj+1] = y01*y01 + y11*y11 + y21*y21 + y31*y31;
    }
    RQ_REDUCE(ps, 2*NT8);
    RQ_REDUCE(pq, 2*NT8);
    __syncthreads();
    float* wsum = (float*)sm;
    float* wsq  = wsum + 8 * NCH;
    if (lane < 4) {
#pragma unroll
        for (int nj = 0; nj < NT8; nj++) {
            int col = n0 + nj*8 + cq;
            wsum[wid*NCH + col]   = ps[2*nj];
            wsum[wid*NCH + col+1] = ps[2*nj+1];
            wsq[wid*NCH + col]    = pq[2*nj];
            wsq[wid*NCH + col+1]  = pq[2*nj+1];
        }
    }
    __syncthreads();
    if (t < NCH) {
        int wb = (t >= 32) ? 4 : 0;
        float s = 0.f, q = 0.f;
#pragma unroll
        for (int w2 = 0; w2 < 4; w2++) {
            s += wsum[(wb+w2)*NCH + t];
            q += wsq[(wb+w2)*NCH + t];
        }
        atomicAdd(&g_sum[1][t], (double)s);
        atomicAdd(&g_sq[1][t],  (double)q);
    }
}

// ---------------- layer 3: HMMA fp16 GEMM + shfl stats + per-query max/min ---
__global__ __launch_bounds__(256) void mm3_kernel(const float* __restrict__ w,
                                                  const float* __restrict__ bias)
{
    constexpr int NCH = 128;
    constexpr int ACH = 128 * 32;
    constexpr int NKC = 8;
    constexpr int NKB = 4;
    constexpr int ABYTES = NKC * ACH;       // 32768
    constexpr int BCH = NCH * 32;
    constexpr int BBYTES = NKB * BCH;       // 16384
    constexpr int NT8 = 8, NB4 = 4;

    extern __shared__ char dsm[];
    uint32_t raw = smem_u32(dsm);
    uint32_t abase = (raw + 1023) & ~1023u;
    char* sm  = dsm + (abase - raw);
    char* Bsm = sm + ABYTES;
    uint32_t bbase = abase + ABYTES;
    float* sh_bias = (float*)(Bsm + BBYTES);
    float* sh_sc = sh_bias + NCH;
    float* sh_sf = sh_sc + 64;

    int t = threadIdx.x;
    int wid = t >> 5, lane = t & 31;
    size_t pos0 = (size_t)blockIdx.x * 128;

    if (t < NCH) sh_bias[t] = bias[t];
    if (t < 64) { sh_sc[t] = g_scale[1][t]; sh_sf[t] = g_shift[1][t]; }
    __syncthreads();

    {
        int r = t >> 1, h = t & 1;
        uint32_t sw = SWZ(r);
        const float4* xrow = (const float4*)(g_y2 + (pos0 + r) * 64) + h * 8;
#pragma unroll
        for (int g = 0; g < 8; g++) {
            float4 v = xrow[g];
            int c = h * 32 + g * 4;
            float a0 = fmaxf(fmaf(v.x, sh_sc[c+0], sh_sf[c+0]), 0.f);
            float a1 = fmaxf(fmaf(v.y, sh_sc[c+1], sh_sf[c+1]), 0.f);
            float a2 = fmaxf(fmaf(v.z, sh_sc[c+2], sh_sf[c+2]), 0.f);
            float a3 = fmaxf(fmaf(v.w, sh_sc[c+3], sh_sf[c+3]), 0.f);
            uint32_t h01, l01, h23, l23;
            split_f16(a0, a1, h01, l01);
            split_f16(a2, a3, h23, l23);
            uint32_t off = (uint32_t)(c >> 4) * ACH + (uint32_t)r * 32
                         + ((uint32_t)((c & 15) * 2) ^ sw);
            *(uint2*)(sm + off)           = make_uint2(h01, h23);
            *(uint2*)(sm + off + 4 * ACH) = make_uint2(l01, l23);
        }
    }
    {
        int r = t >> 1, sub = t & 1;
        uint32_t sw = SWZ(r);
        const float4* wrow = (const float4*)(w + r * 64 + sub * 32);
#pragma unroll
        for (int g = 0; g < 8; g++) {
            float4 v = wrow[g];
            int c = sub * 32 + g * 4;
            uint32_t h01 = pack_f16(v.x, v.y);
            uint32_t h23 = pack_f16(v.z, v.w);
            uint32_t off = (uint32_t)(c >> 4) * BCH + (uint32_t)r * 32
                         + ((uint32_t)((c & 15) * 2) ^ sw);
            *(uint2*)(Bsm + off) = make_uint2(h01, h23);
        }
    }
    __syncthreads();

    int m0 = (wid & 3) * 32;
    int n0 = (wid >> 2) * 64;

    float acc[2][NT8][4];
#pragma unroll
    for (int mi = 0; mi < 2; mi++)
#pragma unroll
        for (int nj = 0; nj < NT8; nj++)
#pragma unroll
            for (int e = 0; e < 4; e++) acc[mi][nj][e] = 0.f;

    uint32_t a_addr[2], b_addr[NB4];
#pragma unroll
    for (int mi = 0; mi < 2; mi++) {
        uint32_t row = (uint32_t)(m0 + mi*16 + (lane & 15));
        a_addr[mi] = abase + row * 32 + (((uint32_t)(lane >> 4) << 4) ^ SWZ(row));
    }
#pragma unroll
    for (int nj = 0; nj < NB4; nj++) {
        uint32_t row = (uint32_t)(n0 + nj*16 + (lane & 7) + ((lane >> 4) << 3));
        b_addr[nj] = bbase + row * 32 + ((((uint32_t)(lane >> 3) & 1u) << 4) ^ SWZ(row));
    }

#pragma unroll
    for (int kc = 0; kc < NKC; kc++) {
        int bkc = kc & (NKB - 1);
        uint32_t af[2][4];
        ldm4(a_addr[0] + kc * ACH, af[0]);
        ldm4(a_addr[1] + kc * ACH, af[1]);
        uint32_t bf[NT8][2];
#pragma unroll
        for (int nj = 0; nj < NB4; nj++) {
            uint32_t tmp[4];
            ldm4(b_addr[nj] + bkc * BCH, tmp);
            bf[2*nj][0] = tmp[0]; bf[2*nj][1] = tmp[1];
            bf[2*nj+1][0] = tmp[2]; bf[2*nj+1][1] = tmp[3];
        }
#pragma unroll
        for (int mi = 0; mi < 2; mi++)
#pragma unroll
            for (int nj = 0; nj < NT8; nj++)
                mma_f16(acc[mi][nj], af[mi], bf[nj]);
    }

    // ---- epilogue: bias, shfl stats, per-query max/min (no global y3) ----
    int rq = lane >> 2, cq = (lane & 3) * 2;
    int q = wid & 3;
    float ps[2*NT8], pq[2*NT8];
    float tmax[NT8][2], tmin[NT8][2];
#pragma unroll
    for (int nj = 0; nj < NT8; nj++) {
        int col = n0 + nj*8 + cq;
        float b0 = sh_bias[col], b1 = sh_bias[col+1];
        float y00 = acc[0][nj][0] + b0, y01 = acc[0][nj][1] + b1;
        float y10 = acc[0][nj][2] + b0, y11 = acc[0][nj][3] + b1;
        float y20 = acc[1][nj][0] + b0, y21 = acc[1][nj][1] + b1;
        float y30 = acc[1][nj][2] + b0, y31 = acc[1][nj][3] + b1;
        tmax[nj][0] = fmaxf(fmaxf(y00, y10), fmaxf(y20, y30));
        tmax[nj][1] = fmaxf(fmaxf(y01, y11), fmaxf(y21, y31));
        tmin[nj][0] = fminf(fminf(y00, y10), fminf(y20, y30));
        tmin[nj][1] = fminf(fminf(y01, y11), fminf(y21, y31));
        ps[2*nj]   = y00 + y10 + y20 + y30;
        ps[2*nj+1] = y01 + y11 + y21 + y31;
        pq[2*nj]   = y00*y00 + y10*y10 + y20*y20 + y30*y30;
        pq[2*nj+1] = y01*y01 + y11*y11 + y21*y21 + y31*y31;
    }
    RQ_REDUCE(ps, 2*NT8);
    RQ_REDUCE(pq, 2*NT8);
    __syncthreads();              // all A/B smem reads complete; reuse regions

    float* shmx = (float*)sm;                    // 16 KB (A region): [q*8+rq][128]
    float* shmn = (float*)(sm + 16384);          // 16 KB (A region)
    float* wsum = (float*)(sm + 32768);          // 4 KB: [8][128]
    float* wsq  = (float*)(sm + 36864);          // 4 KB
#pragma unroll
    for (int nj = 0; nj < NT8; nj++) {
        int col = n0 + nj*8 + cq;
        int idx = (q * 8 + rq) * 128 + col;
        *(float2*)&shmx[idx] = make_float2(tmax[nj][0], tmax[nj][1]);
        *(float2*)&shmn[idx] = make_float2(tmin[nj][0], tmin[nj][1]);
    }
    if (lane < 4) {
#pragma unroll
        for (int nj = 0; nj < NT8; nj++) {
            int col = n0 + nj*8 + cq;
            wsum[wid*NCH + col]   = ps[2*nj];
            wsum[wid*NCH + col+1] = ps[2*nj+1];
            wsq[wid*NCH + col]    = pq[2*nj];
            wsq[wid*NCH + col+1]  = pq[2*nj+1];
        }
    }
    __syncthreads();

    if (t < 128) {
        int wb = (t >= 64) ? 4 : 0;
        float s = 0.f, qq = 0.f;
#pragma unroll
        for (int w2 = 0; w2 < 4; w2++) {
            s += wsum[(wb+w2)*NCH + t];
            qq += wsq[(wb+w2)*NCH + t];
        }
        atomicAdd(&g_sum[2][t], (double)s);
        atomicAdd(&g_sq[2][t],  (double)qq);
    }
#pragma unroll
    for (int u = t; u < 512; u += 256) {
        int uq = u >> 7, col = u & 127;
        float m = shmx[(uq * 8) * 128 + col];
        float n = shmn[(uq * 8) * 128 + col];
#pragma unroll
        for (int p = 1; p < 8; p++) {
            m = fmaxf(m, shmx[(uq * 8 + p) * 128 + col]);
            n = fminf(n, shmn[(uq * 8 + p) * 128 + col]);
        }
        size_t gq = (size_t)blockIdx.x * 4 + uq;
        g_mx[(size_t)col * QTOT + gq] = m;
        g_mn[(size_t)col * QTOT + gq] = n;
    }
}

// ---------------- final: affine+relu on (max,min), coalesced -----------------
__global__ void final_kernel(float* __restrict__ out) {
    int ch = blockIdx.x >> 6;
    int q  = ((blockIdx.x & 63) << 8) + threadIdx.x;
    float sc = g_scale[2][ch], sh = g_shift[2][ch];
    float mx = g_mx[(size_t)ch * QTOT + q];
    float mn = g_mn[(size_t)ch * QTOT + q];
    float v = fmaxf(fmaxf(fmaf(sc, mx, sh), fmaf(sc, mn, sh)), 0.f);
    int b = q >> 10, s = q & 1023;
    out[OUT_OFF + ((size_t)b * 128 + ch) * SS + s] = v;
}

// ---------------- launcher ----------------------------------------------------
extern "C" void kernel_launch(void* const* d_in, const int* in_sizes, int n_in,
                              void* d_out, int out_size) {
    (void)in_sizes; (void)n_in; (void)out_size;
    const float* xyz    = (const float*)d_in[0];
    const float* points = (const float*)d_in[1];
    const float* w1  = (const float*)d_in[2];
    const float* b1  = (const float*)d_in[3];
    const float* g1  = (const float*)d_in[4];
    const float* be1 = (const float*)d_in[5];
    const float* w2  = (const float*)d_in[6];
    const float* b2  = (const float*)d_in[7];
    const float* g2  = (const float*)d_in[8];
    const float* be2 = (const float*)d_in[9];
    const float* w3  = (const float*)d_in[10];
    const float* b3  = (const float*)d_in[11];
    const float* g3  = (const float*)d_in[12];
    const float* be3 = (const float*)d_in[13];
    float* out = (float*)d_out;

    const int FPSSM = NN * 3 * 4;                   // 98304
    const int DYN1 = 1024 + 40960 + 10240 + 1024;   // 53248
    const int DYN2 = 1024 + 32768 + 8192 + 2048;    // 44032
    const int DYN3 = 1024 + 32768 + 16384 + 2048;   // 52224
    cudaFuncSetAttribute(fps_kernel, cudaFuncAttributeMaxDynamicSharedMemorySize, FPSSM);
    cudaFuncSetAttribute(mm1_kernel, cudaFuncAttributeMaxDynamicSharedMemorySize, DYN1);
    cudaFuncSetAttribute(mm2_kernel, cudaFuncAttributeMaxDynamicSharedMemorySize, DYN2);
    cudaFuncSetAttribute(mm3_kernel, cudaFuncAttributeMaxDynamicSharedMemorySize, DYN3);

    init_kernel<<<1, 512>>>();
    fps_kernel<<<BB, 1024, FPSSM>>>(xyz);
    gather_newxyz_kernel<<<(QTOT + 255) / 256, 256>>>(xyz, out);
    qb_kernel<<<(QTOT) / 8, 256>>>(xyz);

    mm1_kernel<<<MTOT / 128, 256, DYN1>>>(xyz, points, out, w1, b1);
    stats_kernel<<<1, 128>>>(0, g1, be1, 64);

    mm2_kernel<<<MTOT / 128, 256, DYN2>>>(w2, b2);
    stats_kernel<<<1, 128>>>(1, g2, be2, 64);

    mm3_kernel<<<MTOT / 128, 256, DYN3>>>(w3, b3);
    stats_kernel<<<1, 128>>>(2, g3, be3, 128);

    final_kernel<<<128 * 64, 256>>>(out);
}